// round 11
// baseline (speedup 1.0000x reference)
#include <cuda_runtime.h>
#include <cuda_bf16.h>
#include <cstdint>
#include <math.h>

// Problem constants
#define LL 128
#define BB 512
#define DD 512
#define SS 128
#define LB (LL * BB)   // 65536

// -------- device scratch --------
__device__ __align__(16) float          g_colbias[SS];
__device__ __align__(16) float          g_rvar[DD];
__device__ __align__(16) float          g_xq[LB];               // -0.5*sum x^2/var
__device__ __align__(16) __nv_bfloat16  g_Xs[(size_t)LB * DD];  // X in bf16 (64 MB)
__device__ __align__(16) __nv_bfloat16  g_Mv[SS * DD];          // mu/var bf16, [s][d]
__device__ __align__(16) __nv_bfloat16  g_At[SS * SS];          // A^T bf16
// E in mma-fragment layout, lane-major: [((l*32 + btile)*16 + n)*32 + lane]
__device__ __align__(16) uint2          g_Efrag[(size_t)LL * 32 * 16 * 32]; // 16 MB
__device__ __align__(16) float          g_dmaxT[BB * LL];       // dmax transposed: [b][l]
__device__ __align__(16) float          g_perb[BB];

#define LOG2PI 1.8378770664093453f
#define LOGPI_INIT (-4.852030263919617f)   // -log(128)

// ---- fast exp on the FMA pipe (x <= 0 expected; flushes below -80) ----
__device__ __forceinline__ float fexp(float x) {
    float t = fmaf(x, 1.4426950408889634f, 12582912.0f);
    int   ni = __float_as_int(t) - 0x4B400000;
    float n  = t - 12582912.0f;
    float f  = fmaf(x, 1.4426950408889634f, -n);
    float r  = 0.0013333558f;
    r = fmaf(r, f, 0.0096181291f);
    r = fmaf(r, f, 0.0555041087f);
    r = fmaf(r, f, 0.2402264689f);
    r = fmaf(r, f, 0.6931471806f);
    r = fmaf(r, f, 1.0f);
    float res = __int_as_float(__float_as_int(r) + (ni << 23));
    return (x > -80.0f) ? res : 0.0f;
}

__device__ __forceinline__ uint32_t pk(__nv_bfloat162 v) { return *reinterpret_cast<uint32_t*>(&v); }
__device__ __forceinline__ __nv_bfloat162 upk(uint32_t v) { return *reinterpret_cast<__nv_bfloat162*>(&v); }
__device__ __forceinline__ uint32_t smem_u32(const void* p) {
    return (uint32_t)__cvta_generic_to_shared(p);
}

__device__ __forceinline__ void mma_bf16(float& c0, float& c1, float& c2, float& c3,
                                         uint32_t a0, uint32_t a1, uint32_t a2, uint32_t a3,
                                         uint32_t b0, uint32_t b1) {
    asm volatile(
        "mma.sync.aligned.m16n8k16.row.col.f32.bf16.bf16.f32 "
        "{%0,%1,%2,%3}, {%4,%5,%6,%7}, {%8,%9}, {%0,%1,%2,%3};\n"
        : "+f"(c0), "+f"(c1), "+f"(c2), "+f"(c3)
        : "r"(a0), "r"(a1), "r"(a2), "r"(a3), "r"(b0), "r"(b1));
}

__device__ __forceinline__ void ldmx4(uint32_t& r0, uint32_t& r1, uint32_t& r2, uint32_t& r3,
                                      uint32_t addr) {
    asm volatile("ldmatrix.sync.aligned.m8n8.x4.shared.b16 {%0,%1,%2,%3}, [%4];"
                 : "=r"(r0), "=r"(r1), "=r"(r2), "=r"(r3) : "r"(addr));
}

// =====================================================================
// Kernel 1: preprocessing (1 block, 512 threads)
// =====================================================================
__global__ void prep_kernel(const float* __restrict__ tparams,
                            const float* __restrict__ means,
                            const float* __restrict__ var) {
    __shared__ float sred[512];
    int t = threadIdx.x;

    float v = var[t];
    g_rvar[t] = 1.0f / v;
    sred[t] = logf(v);
    __syncthreads();
    for (int off = 256; off > 0; off >>= 1) {
        if (t < off) sred[t] += sred[t + off];
        __syncthreads();
    }
    float slv = sred[0];
    float c = -256.0f * LOG2PI - 0.5f * slv;

    int q   = t & 3;      // 0..3
    int grp = t >> 2;     // 0..127  (row i)

    // col bias
    {
        float mq = 0.f;
        for (int d = q; d < DD; d += 4) {
            float m = means[grp * DD + d];
            mq += m * m * g_rvar[d];
        }
        mq += __shfl_xor_sync(0xffffffffu, mq, 1);
        mq += __shfl_xor_sync(0xffffffffu, mq, 2);
        if (q == 0) g_colbias[grp] = c - 0.5f * mq;
    }

    // At[j][i] = exp(tparams[i][j] - lse_j'(tparams[i][:]))
    {
        float mx = -1e30f;
        for (int jj = q; jj < SS; jj += 4) mx = fmaxf(mx, tparams[grp * SS + jj]);
        mx = fmaxf(mx, __shfl_xor_sync(0xffffffffu, mx, 1));
        mx = fmaxf(mx, __shfl_xor_sync(0xffffffffu, mx, 2));
        float se = 0.f;
        for (int jj = q; jj < SS; jj += 4) se += __expf(tparams[grp * SS + jj] - mx);
        se += __shfl_xor_sync(0xffffffffu, se, 1);
        se += __shfl_xor_sync(0xffffffffu, se, 2);
        float lse = mx + __logf(se);
        for (int jj = q; jj < SS; jj += 4)
            g_At[jj * SS + grp] = __float2bfloat16(__expf(tparams[grp * SS + jj] - lse));
    }

    // Mv = mu / var in bf16
    for (int idx = t; idx < SS * DD; idx += 512) {
        int d = idx & (DD - 1);
        g_Mv[idx] = __float2bfloat16(means[idx] * g_rvar[d]);
    }
}

// =====================================================================
// Kernel 2: per-row -0.5*sum(x^2/var) + bf16 cast of X (DRAM-bound)
// =====================================================================
__global__ __launch_bounds__(256) void xqcast_kernel(const float* __restrict__ sents) {
    __shared__ __align__(16) float srv[DD];
    int tid = threadIdx.x;
    for (int i = tid; i < DD; i += 256) srv[i] = g_rvar[i];
    __syncthreads();

    int warp = tid >> 5, lane = tid & 31;
    int row = blockIdx.x * 8 + warp;

    const float4* src = reinterpret_cast<const float4*>(sents + (size_t)row * DD);
    float sum = 0.f;
#pragma unroll
    for (int c = 0; c < 4; ++c) {
        int idx4 = c * 32 + lane;   // float4 index in row (128 per row)
        float4 x  = src[idx4];
        float4 rv = *reinterpret_cast<const float4*>(&srv[idx4 * 4]);
        sum += x.x * x.x * rv.x + x.y * x.y * rv.y + x.z * x.z * rv.z + x.w * x.w * rv.w;
        __nv_bfloat162 p0 = __float22bfloat162_rn(make_float2(x.x, x.y));
        __nv_bfloat162 p1 = __float22bfloat162_rn(make_float2(x.z, x.w));
        __nv_bfloat162* dst = reinterpret_cast<__nv_bfloat162*>(&g_Xs[(size_t)row * DD + idx4 * 4]);
        dst[0] = p0;
        dst[1] = p1;
    }
#pragma unroll
    for (int off = 16; off > 0; off >>= 1)
        sum += __shfl_xor_sync(0xffffffffu, sum, off);
    if (lane == 0) g_xq[row] = -0.5f * sum;
}

// =====================================================================
// Kernel 3: density GEMM (copy-only staging) -> E (fragment layout) + dmaxT
// =====================================================================
#define SMSTRIDE 72

__global__ __launch_bounds__(256) void density_kernel() {
    __shared__ __align__(16) __nv_bfloat16 sA[128 * SMSTRIDE];
    __shared__ __align__(16) __nv_bfloat16 sB[128 * SMSTRIDE];
    __shared__ float scb[128];

    int tid  = threadIdx.x;
    int warp = tid >> 5, lane = tid & 31;
    int g = lane >> 2, tg = lane & 3;
    int mbase = blockIdx.x * 128;

    if (tid < 128) scb[tid] = g_colbias[tid];

    float acc[16][4];
#pragma unroll
    for (int n = 0; n < 16; ++n)
#pragma unroll
        for (int k = 0; k < 4; ++k) acc[n][k] = 0.f;

    __syncthreads();

    for (int ko = 0; ko < 8; ++ko) {
#pragma unroll
        for (int k = 0; k < 4; ++k) {
            int idx = tid + k * 256;         // 1024 uint4 total
            int r = idx >> 3, c8 = idx & 7;
            uint4 va = *reinterpret_cast<const uint4*>(&g_Xs[(size_t)(mbase + r) * DD + ko * 64 + c8 * 8]);
            *reinterpret_cast<uint4*>(&sA[r * SMSTRIDE + c8 * 8]) = va;
        }
#pragma unroll
        for (int k = 0; k < 4; ++k) {
            int idx = tid + k * 256;
            int r = idx >> 3, c8 = idx & 7;
            uint4 vb = *reinterpret_cast<const uint4*>(&g_Mv[(size_t)r * DD + ko * 64 + c8 * 8]);
            *reinterpret_cast<uint4*>(&sB[r * SMSTRIDE + c8 * 8]) = vb;
        }
        __syncthreads();

#pragma unroll
        for (int ks = 0; ks < 4; ++ks) {
            int k0 = ks * 16 + tg * 2;
            uint32_t a0 = *reinterpret_cast<const uint32_t*>(&sA[(warp * 16 + g)     * SMSTRIDE + k0]);
            uint32_t a1 = *reinterpret_cast<const uint32_t*>(&sA[(warp * 16 + g + 8) * SMSTRIDE + k0]);
            uint32_t a2 = *reinterpret_cast<const uint32_t*>(&sA[(warp * 16 + g)     * SMSTRIDE + k0 + 8]);
            uint32_t a3 = *reinterpret_cast<const uint32_t*>(&sA[(warp * 16 + g + 8) * SMSTRIDE + k0 + 8]);
#pragma unroll
            for (int n = 0; n < 16; ++n) {
                uint32_t b0 = *reinterpret_cast<const uint32_t*>(&sB[(n * 8 + g) * SMSTRIDE + k0]);
                uint32_t b1 = *reinterpret_cast<const uint32_t*>(&sB[(n * 8 + g) * SMSTRIDE + k0 + 8]);
                mma_bf16(acc[n][0], acc[n][1], acc[n][2], acc[n][3], a0, a1, a2, a3, b0, b1);
            }
        }
        __syncthreads();
    }

    int r0l = warp * 16 + g;
    int r0 = mbase + r0l;
    int r1 = r0 + 8;
    float xq0 = g_xq[r0], xq1 = g_xq[r1];

    float mx0 = -1e30f, mx1 = -1e30f;
#pragma unroll
    for (int n = 0; n < 16; ++n) {
        int col = n * 8 + tg * 2;
        float cb0 = scb[col], cb1 = scb[col + 1];
        acc[n][0] += cb0; acc[n][1] += cb1;
        acc[n][2] += cb0; acc[n][3] += cb1;
        mx0 = fmaxf(mx0, fmaxf(acc[n][0], acc[n][1]));
        mx1 = fmaxf(mx1, fmaxf(acc[n][2], acc[n][3]));
    }
    mx0 = fmaxf(mx0, __shfl_xor_sync(0xffffffffu, mx0, 1));
    mx0 = fmaxf(mx0, __shfl_xor_sync(0xffffffffu, mx0, 2));
    mx1 = fmaxf(mx1, __shfl_xor_sync(0xffffffffu, mx1, 1));
    mx1 = fmaxf(mx1, __shfl_xor_sync(0xffffffffu, mx1, 2));

    // E fragment write, lane-major: [((l*32+btile)*16 + n)*32 + lane]
    int b = r0 & (BB - 1);
    int l = r0 >> 9;
    int btile = b >> 4;
    uint2* eout = &g_Efrag[((size_t)(l * 32 + btile) * 16) * 32 + lane];
#pragma unroll
    for (int n = 0; n < 16; ++n) {
        __nv_bfloat162 e01 = __floats2bfloat162_rn(fexp(acc[n][0] - mx0), fexp(acc[n][1] - mx0));
        __nv_bfloat162 e23 = __floats2bfloat162_rn(fexp(acc[n][2] - mx1), fexp(acc[n][3] - mx1));
        eout[n * 32] = make_uint2(pk(e01), pk(e23));
    }
    if (tg == 0) {
        g_dmaxT[(size_t)b * LL + l]       = mx0 + xq0;
        g_dmaxT[(size_t)(b + 8) * LL + l] = mx1 + xq1;
    }
}

// =====================================================================
// Kernel 4: forward recurrence — 8-warp n-split, E prefetched one step
// ahead, split accumulator chains (4+4 kt) to halve HMMA RAW depth.
// =====================================================================
#define ATSTRIDE 136
#define PSTRIDE  136

#define OFF_AT    0
#define OFF_P0    34816
#define OFF_P1    (OFF_P0 + 4352)
#define OFF_DMAX  (OFF_P1 + 4352)
#define OFF_MK    (OFF_DMAX + 8192)
#define OFF_SRN   (OFF_MK + 2048)
#define OFF_SSUM  (OFF_SRN + 512)
#define OFF_SM    (OFF_SSUM + 512)
#define RECUR_SMEM (OFF_SM + 64)

__global__ __launch_bounds__(256) void recur_kernel(const float* __restrict__ masks) {
    extern __shared__ __align__(16) unsigned char dyn[];
    __nv_bfloat16* sAt = reinterpret_cast<__nv_bfloat16*>(dyn + OFF_AT);
    __nv_bfloat16* sp0 = reinterpret_cast<__nv_bfloat16*>(dyn + OFF_P0);
    __nv_bfloat16* sp1 = reinterpret_cast<__nv_bfloat16*>(dyn + OFF_P1);
    float* sdmax = reinterpret_cast<float*>(dyn + OFF_DMAX);
    unsigned char* smk = dyn + OFF_MK;
    float (*srn)[16]  = reinterpret_cast<float (*)[16]>(dyn + OFF_SRN);
    float (*ssum)[16] = reinterpret_cast<float (*)[16]>(dyn + OFF_SSUM);
    float* sM = reinterpret_cast<float*>(dyn + OFF_SM);

    int tid   = threadIdx.x;
    int lane  = tid & 31, w = tid >> 5;
    int btile = blockIdx.x;
    int g = lane >> 2, tg = lane & 3;

    {
        const uint4* src = reinterpret_cast<const uint4*>(g_At);
        for (int idx = tid; idx < 2048; idx += 256) {
            int j = idx >> 4, c = idx & 15;
            *reinterpret_cast<uint4*>(&sAt[j * ATSTRIDE + c * 8]) = src[idx];
        }
    }
    for (int idx = tid; idx < 2048; idx += 256) {
        int bi = idx >> 7, l = idx & 127;
        sdmax[l * 16 + bi] = g_dmaxT[(size_t)(btile * 16 + bi) * LL + l];
        smk[l * 16 + bi]   = (masks[l * BB + btile * 16 + bi] >= 0.5f) ? 1 : 0;
    }
    __syncthreads();

    // hoist B fragments: warp w covers n-pair group np = w
    int q = lane >> 3, r = lane & 7;
    int rowb = ((q & 2) ? 8 : 0) + r;
    int kofs = (q & 1) ? 8 : 0;
    uint32_t bbase = smem_u32(&sAt[rowb * ATSTRIDE + kofs]);
    uint32_t bf[32];
#pragma unroll
    for (int kt = 0; kt < 8; ++kt) {
        ldmx4(bf[kt * 4 + 0], bf[kt * 4 + 1], bf[kt * 4 + 2], bf[kt * 4 + 3],
              bbase + w * (16 * ATSTRIDE * 2) + kt * 32);
    }

    const uint2* __restrict__ Eb = g_Efrag + (size_t)btile * 512 + lane;

    uint32_t pv01[2], pv23[2];
#pragma unroll
    for (int lt = 0; lt < 2; ++lt) {
        uint2 e = Eb[(2 * w + lt) * 32];
        pv01[lt] = e.x;
        pv23[lt] = e.y;
    }
#pragma unroll
    for (int lt = 0; lt < 2; ++lt) {
        int col = (2 * w + lt) * 8 + 2 * tg;
        *reinterpret_cast<uint32_t*>(&sp0[g * PSTRIDE + col])       = pv01[lt];
        *reinterpret_cast<uint32_t*>(&sp0[(g + 8) * PSTRIDE + col]) = pv23[lt];
    }
    float Mg = LOGPI_INIT + sdmax[g];
    float Mh = LOGPI_INIT + sdmax[g + 8];

    // prefetch E for step 1 (hidden behind the init barrier + first LDSMs)
    uint2 en[2];
    {
        const uint2* Ep = Eb + (size_t)1 * 16384;
        en[0] = Ep[(2 * w + 0) * 32];
        en[1] = Ep[(2 * w + 1) * 32];
    }
    __syncthreads();

    int arow = (lane & 7) + ((lane & 8) ? 8 : 0);
    int akof = (lane & 16) ? 8 : 0;
    uint32_t abase[2];
    abase[0] = smem_u32(&sp0[arow * PSTRIDE + akof]);
    abase[1] = smem_u32(&sp1[arow * PSTRIDE + akof]);

    int buf = 0;
    for (int l = 1; l < LL; ++l) {
        // consume prefetched E; immediately prefetch next step's
        uint2 ef[2];
        ef[0] = en[0];
        ef[1] = en[1];
        if (l + 1 < LL) {
            const uint2* Ep = Eb + (size_t)(l + 1) * 16384;
            en[0] = Ep[(2 * w + 0) * 32];
            en[1] = Ep[(2 * w + 1) * 32];
        }

        uint32_t af[32];
#pragma unroll
        for (int kt = 0; kt < 8; ++kt)
            ldmx4(af[kt * 4 + 0], af[kt * 4 + 1], af[kt * 4 + 2], af[kt * 4 + 3],
                  abase[buf] + kt * 32);

        float dm0 = sdmax[l * 16 + g];
        float dm1 = sdmax[l * 16 + g + 8];
        int mk0 = smk[l * 16 + g];
        int mk1 = smk[l * 16 + g + 8];

        // two independent accumulator chains (kt 0-3, kt 4-7)
        float accA[2][4], accB[2][4];
#pragma unroll
        for (int n = 0; n < 2; ++n)
#pragma unroll
            for (int k = 0; k < 4; ++k) { accA[n][k] = 0.f; accB[n][k] = 0.f; }

#pragma unroll
        for (int kt = 0; kt < 4; ++kt) {
            uint32_t a0 = af[kt * 4 + 0], a1 = af[kt * 4 + 1];
            uint32_t a2 = af[kt * 4 + 2], a3 = af[kt * 4 + 3];
            const uint32_t* bb = &bf[kt * 4];
            mma_bf16(accA[0][0], accA[0][1], accA[0][2], accA[0][3],
                     a0, a1, a2, a3, bb[0], bb[1]);
            mma_bf16(accA[1][0], accA[1][1], accA[1][2], accA[1][3],
                     a0, a1, a2, a3, bb[2], bb[3]);
        }
#pragma unroll
        for (int kt = 4; kt < 8; ++kt) {
            uint32_t a0 = af[kt * 4 + 0], a1 = af[kt * 4 + 1];
            uint32_t a2 = af[kt * 4 + 2], a3 = af[kt * 4 + 3];
            const uint32_t* bb = &bf[kt * 4];
            mma_bf16(accB[0][0], accB[0][1], accB[0][2], accB[0][3],
                     a0, a1, a2, a3, bb[0], bb[1]);
            mma_bf16(accB[1][0], accB[1][1], accB[1][2], accB[1][3],
                     a0, a1, a2, a3, bb[2], bb[3]);
        }

        float acc[2][4];
#pragma unroll
        for (int n = 0; n < 2; ++n)
#pragma unroll
            for (int k = 0; k < 4; ++k) acc[n][k] = accA[n][k] + accB[n][k];

        // epilogue: * E, mask blend (packed select)
#pragma unroll
        for (int lt = 0; lt < 2; ++lt) {
            float2 eg = __bfloat1622float2(upk(ef[lt].x));
            float2 eh = __bfloat1622float2(upk(ef[lt].y));
            uint32_t u01 = pk(__floats2bfloat162_rn(acc[lt][0] * eg.x, acc[lt][1] * eg.y));
            uint32_t u23 = pk(__floats2bfloat162_rn(acc[lt][2] * eh.x, acc[lt][3] * eh.y));
            if (!mk0) u01 = pv01[lt];
            if (!mk1) u23 = pv23[lt];
            pv01[lt] = u01;
            pv23[lt] = u23;
        }
        if (mk0) Mg += dm0;
        if (mk1) Mh += dm1;

        // periodic renorm (cross-warp max -> fold into M)
        if ((l & 7) == 0) {
            float mg = 1e-30f, mh = 1e-30f;
#pragma unroll
            for (int lt = 0; lt < 2; ++lt) {
                float2 v01 = __bfloat1622float2(upk(pv01[lt]));
                float2 v23 = __bfloat1622float2(upk(pv23[lt]));
                mg = fmaxf(mg, fmaxf(v01.x, v01.y));
                mh = fmaxf(mh, fmaxf(v23.x, v23.y));
            }
            mg = fmaxf(mg, __shfl_xor_sync(0xffffffffu, mg, 1));
            mg = fmaxf(mg, __shfl_xor_sync(0xffffffffu, mg, 2));
            mh = fmaxf(mh, __shfl_xor_sync(0xffffffffu, mh, 1));
            mh = fmaxf(mh, __shfl_xor_sync(0xffffffffu, mh, 2));
            if (tg == 0) { srn[w][g] = mg; srn[w][g + 8] = mh; }
            __syncthreads();
#pragma unroll
            for (int ww = 0; ww < 8; ++ww) {
                mg = fmaxf(mg, srn[ww][g]);
                mh = fmaxf(mh, srn[ww][g + 8]);
            }
            float rg = 1.f / mg, rh = 1.f / mh;
#pragma unroll
            for (int lt = 0; lt < 2; ++lt) {
                float2 v01 = __bfloat1622float2(upk(pv01[lt]));
                float2 v23 = __bfloat1622float2(upk(pv23[lt]));
                pv01[lt] = pk(__floats2bfloat162_rn(v01.x * rg, v01.y * rg));
                pv23[lt] = pk(__floats2bfloat162_rn(v23.x * rh, v23.y * rh));
            }
            Mg += __logf(mg);
            Mh += __logf(mh);
        }

        // store own slice to the other buffer, then one barrier
        int nbuf = buf ^ 1;
        {
            __nv_bfloat16* base = nbuf ? sp1 : sp0;
#pragma unroll
            for (int lt = 0; lt < 2; ++lt) {
                int col = (2 * w + lt) * 8 + 2 * tg;
                *reinterpret_cast<uint32_t*>(&base[g * PSTRIDE + col])       = pv01[lt];
                *reinterpret_cast<uint32_t*>(&base[(g + 8) * PSTRIDE + col]) = pv23[lt];
            }
        }
        __syncthreads();
        buf = nbuf;
    }

    float Sg = 0.f, Sh = 0.f;
#pragma unroll
    for (int lt = 0; lt < 2; ++lt) {
        float2 v01 = __bfloat1622float2(upk(pv01[lt]));
        float2 v23 = __bfloat1622float2(upk(pv23[lt]));
        Sg += v01.x + v01.y;
        Sh += v23.x + v23.y;
    }
    Sg += __shfl_xor_sync(0xffffffffu, Sg, 1);
    Sg += __shfl_xor_sync(0xffffffffu, Sg, 2);
    Sh += __shfl_xor_sync(0xffffffffu, Sh, 1);
    Sh += __shfl_xor_sync(0xffffffffu, Sh, 2);
    if (tg == 0) {
        ssum[w][g] = Sg;
        ssum[w][g + 8] = Sh;
        if (w == 0) { sM[g] = Mg; sM[g + 8] = Mh; }
    }
    __syncthreads();
    if (tid < 16) {
        float S = 0.f;
#pragma unroll
        for (int ww = 0; ww < 8; ++ww) S += ssum[ww][tid];
        S = fmaxf(S, 1e-37f);
        g_perb[btile * 16 + tid] = sM[tid] + __logf(S);
    }
}

// =====================================================================
// Kernel 5: deterministic final reduction over 512 batch rows
// =====================================================================
__global__ void finalize_kernel(float* __restrict__ out, int out_size) {
    __shared__ float s[256];
    int t = threadIdx.x;
    s[t] = g_perb[t] + g_perb[t + 256];
    __syncthreads();
    for (int off = 128; off > 0; off >>= 1) {
        if (t < off) s[t] += s[t + off];
        __syncthreads();
    }
    for (int i = t; i < out_size; i += 256)
        if (i != 0) out[i] = 0.f;   // jacobian_loss = 0
    if (t == 0) out[0] = s[0];
}

// =====================================================================
extern "C" void kernel_launch(void* const* d_in, const int* in_sizes, int n_in,
                              void* d_out, int out_size) {
    const float* sents   = (const float*)d_in[0];
    const float* masks   = (const float*)d_in[1];
    const float* tparams = (const float*)d_in[2];
    const float* means   = (const float*)d_in[3];
    const float* var     = (const float*)d_in[4];
    float* out = (float*)d_out;

    cudaFuncSetAttribute(recur_kernel, cudaFuncAttributeMaxDynamicSharedMemorySize, RECUR_SMEM);

    prep_kernel<<<1, 512>>>(tparams, means, var);
    xqcast_kernel<<<LB / 8, 256>>>(sents);
    density_kernel<<<LB / 128, 256>>>();
    recur_kernel<<<32, 256, RECUR_SMEM>>>(masks);
    finalize_kernel<<<1, 256>>>(out, out_size);
}

// round 12
// speedup vs baseline: 1.0109x; 1.0109x over previous
#include <cuda_runtime.h>
#include <cuda_bf16.h>
#include <cstdint>
#include <math.h>

// Problem constants
#define LL 128
#define BB 512
#define DD 512
#define SS 128
#define LB (LL * BB)   // 65536

// -------- device scratch --------
__device__ __align__(16) float          g_colbias[SS];
__device__ __align__(16) float          g_rvar[DD];
__device__ __align__(16) float          g_xq[LB];               // -0.5*sum x^2/var
__device__ __align__(16) __nv_bfloat16  g_Xs[(size_t)LB * DD];  // X in bf16 (64 MB)
__device__ __align__(16) __nv_bfloat16  g_Mv[SS * DD];          // mu/var bf16, [s][d]
__device__ __align__(16) __nv_bfloat16  g_At[SS * SS];          // A^T bf16
// E in mma-fragment layout, lane-major: [((l*32 + btile)*16 + n)*32 + lane]
__device__ __align__(16) uint2          g_Efrag[(size_t)LL * 32 * 16 * 32]; // 16 MB
__device__ __align__(16) float          g_dmaxT[BB * LL];       // dmax transposed: [b][l]
__device__ __align__(16) float          g_perb[BB];

#define LOG2PI 1.8378770664093453f
#define LOGPI_INIT (-4.852030263919617f)   // -log(128)

// ---- fast exp on the FMA pipe (x <= 0 expected; flushes below -80) ----
__device__ __forceinline__ float fexp(float x) {
    float t = fmaf(x, 1.4426950408889634f, 12582912.0f);
    int   ni = __float_as_int(t) - 0x4B400000;
    float n  = t - 12582912.0f;
    float f  = fmaf(x, 1.4426950408889634f, -n);
    float r  = 0.0013333558f;
    r = fmaf(r, f, 0.0096181291f);
    r = fmaf(r, f, 0.0555041087f);
    r = fmaf(r, f, 0.2402264689f);
    r = fmaf(r, f, 0.6931471806f);
    r = fmaf(r, f, 1.0f);
    float res = __int_as_float(__float_as_int(r) + (ni << 23));
    return (x > -80.0f) ? res : 0.0f;
}

__device__ __forceinline__ uint32_t pk(__nv_bfloat162 v) { return *reinterpret_cast<uint32_t*>(&v); }
__device__ __forceinline__ __nv_bfloat162 upk(uint32_t v) { return *reinterpret_cast<__nv_bfloat162*>(&v); }
__device__ __forceinline__ uint32_t smem_u32(const void* p) {
    return (uint32_t)__cvta_generic_to_shared(p);
}

__device__ __forceinline__ void mma_bf16(float& c0, float& c1, float& c2, float& c3,
                                         uint32_t a0, uint32_t a1, uint32_t a2, uint32_t a3,
                                         uint32_t b0, uint32_t b1) {
    asm volatile(
        "mma.sync.aligned.m16n8k16.row.col.f32.bf16.bf16.f32 "
        "{%0,%1,%2,%3}, {%4,%5,%6,%7}, {%8,%9}, {%0,%1,%2,%3};\n"
        : "+f"(c0), "+f"(c1), "+f"(c2), "+f"(c3)
        : "r"(a0), "r"(a1), "r"(a2), "r"(a3), "r"(b0), "r"(b1));
}

__device__ __forceinline__ void ldmx4(uint32_t& r0, uint32_t& r1, uint32_t& r2, uint32_t& r3,
                                      uint32_t addr) {
    asm volatile("ldmatrix.sync.aligned.m8n8.x4.shared.b16 {%0,%1,%2,%3}, [%4];"
                 : "=r"(r0), "=r"(r1), "=r"(r2), "=r"(r3) : "r"(addr));
}

// =====================================================================
// Kernel 1: preprocessing (1 block, 512 threads)
// =====================================================================
__global__ void prep_kernel(const float* __restrict__ tparams,
                            const float* __restrict__ means,
                            const float* __restrict__ var) {
    __shared__ float sred[512];
    int t = threadIdx.x;

    float v = var[t];
    g_rvar[t] = 1.0f / v;
    sred[t] = logf(v);
    __syncthreads();
    for (int off = 256; off > 0; off >>= 1) {
        if (t < off) sred[t] += sred[t + off];
        __syncthreads();
    }
    float slv = sred[0];
    float c = -256.0f * LOG2PI - 0.5f * slv;

    int q   = t & 3;      // 0..3
    int grp = t >> 2;     // 0..127  (row i)

    // col bias
    {
        float mq = 0.f;
        for (int d = q; d < DD; d += 4) {
            float m = means[grp * DD + d];
            mq += m * m * g_rvar[d];
        }
        mq += __shfl_xor_sync(0xffffffffu, mq, 1);
        mq += __shfl_xor_sync(0xffffffffu, mq, 2);
        if (q == 0) g_colbias[grp] = c - 0.5f * mq;
    }

    // At[j][i] = exp(tparams[i][j] - lse_j'(tparams[i][:]))
    {
        float mx = -1e30f;
        for (int jj = q; jj < SS; jj += 4) mx = fmaxf(mx, tparams[grp * SS + jj]);
        mx = fmaxf(mx, __shfl_xor_sync(0xffffffffu, mx, 1));
        mx = fmaxf(mx, __shfl_xor_sync(0xffffffffu, mx, 2));
        float se = 0.f;
        for (int jj = q; jj < SS; jj += 4) se += __expf(tparams[grp * SS + jj] - mx);
        se += __shfl_xor_sync(0xffffffffu, se, 1);
        se += __shfl_xor_sync(0xffffffffu, se, 2);
        float lse = mx + __logf(se);
        for (int jj = q; jj < SS; jj += 4)
            g_At[jj * SS + grp] = __float2bfloat16(__expf(tparams[grp * SS + jj] - lse));
    }

    // Mv = mu / var in bf16
    for (int idx = t; idx < SS * DD; idx += 512) {
        int d = idx & (DD - 1);
        g_Mv[idx] = __float2bfloat16(means[idx] * g_rvar[d]);
    }
}

// =====================================================================
// Kernel 2: per-row -0.5*sum(x^2/var) + bf16 cast of X (DRAM-bound)
// =====================================================================
__global__ __launch_bounds__(256) void xqcast_kernel(const float* __restrict__ sents) {
    __shared__ __align__(16) float srv[DD];
    int tid = threadIdx.x;
    for (int i = tid; i < DD; i += 256) srv[i] = g_rvar[i];
    __syncthreads();

    int warp = tid >> 5, lane = tid & 31;
    int row = blockIdx.x * 8 + warp;

    const float4* src = reinterpret_cast<const float4*>(sents + (size_t)row * DD);
    float sum = 0.f;
#pragma unroll
    for (int c = 0; c < 4; ++c) {
        int idx4 = c * 32 + lane;   // float4 index in row (128 per row)
        float4 x  = src[idx4];
        float4 rv = *reinterpret_cast<const float4*>(&srv[idx4 * 4]);
        sum += x.x * x.x * rv.x + x.y * x.y * rv.y + x.z * x.z * rv.z + x.w * x.w * rv.w;
        __nv_bfloat162 p0 = __float22bfloat162_rn(make_float2(x.x, x.y));
        __nv_bfloat162 p1 = __float22bfloat162_rn(make_float2(x.z, x.w));
        __nv_bfloat162* dst = reinterpret_cast<__nv_bfloat162*>(&g_Xs[(size_t)row * DD + idx4 * 4]);
        dst[0] = p0;
        dst[1] = p1;
    }
#pragma unroll
    for (int off = 16; off > 0; off >>= 1)
        sum += __shfl_xor_sync(0xffffffffu, sum, off);
    if (lane == 0) g_xq[row] = -0.5f * sum;
}

// =====================================================================
// Kernel 3: density GEMM (copy-only staging) -> E (fragment layout) + dmaxT
// =====================================================================
#define SMSTRIDE 72

__global__ __launch_bounds__(256) void density_kernel() {
    __shared__ __align__(16) __nv_bfloat16 sA[128 * SMSTRIDE];
    __shared__ __align__(16) __nv_bfloat16 sB[128 * SMSTRIDE];
    __shared__ float scb[128];

    int tid  = threadIdx.x;
    int warp = tid >> 5, lane = tid & 31;
    int g = lane >> 2, tg = lane & 3;
    int mbase = blockIdx.x * 128;

    if (tid < 128) scb[tid] = g_colbias[tid];

    float acc[16][4];
#pragma unroll
    for (int n = 0; n < 16; ++n)
#pragma unroll
        for (int k = 0; k < 4; ++k) acc[n][k] = 0.f;

    __syncthreads();

    for (int ko = 0; ko < 8; ++ko) {
#pragma unroll
        for (int k = 0; k < 4; ++k) {
            int idx = tid + k * 256;         // 1024 uint4 total
            int r = idx >> 3, c8 = idx & 7;
            uint4 va = *reinterpret_cast<const uint4*>(&g_Xs[(size_t)(mbase + r) * DD + ko * 64 + c8 * 8]);
            *reinterpret_cast<uint4*>(&sA[r * SMSTRIDE + c8 * 8]) = va;
        }
#pragma unroll
        for (int k = 0; k < 4; ++k) {
            int idx = tid + k * 256;
            int r = idx >> 3, c8 = idx & 7;
            uint4 vb = *reinterpret_cast<const uint4*>(&g_Mv[(size_t)r * DD + ko * 64 + c8 * 8]);
            *reinterpret_cast<uint4*>(&sB[r * SMSTRIDE + c8 * 8]) = vb;
        }
        __syncthreads();

#pragma unroll
        for (int ks = 0; ks < 4; ++ks) {
            int k0 = ks * 16 + tg * 2;
            uint32_t a0 = *reinterpret_cast<const uint32_t*>(&sA[(warp * 16 + g)     * SMSTRIDE + k0]);
            uint32_t a1 = *reinterpret_cast<const uint32_t*>(&sA[(warp * 16 + g + 8) * SMSTRIDE + k0]);
            uint32_t a2 = *reinterpret_cast<const uint32_t*>(&sA[(warp * 16 + g)     * SMSTRIDE + k0 + 8]);
            uint32_t a3 = *reinterpret_cast<const uint32_t*>(&sA[(warp * 16 + g + 8) * SMSTRIDE + k0 + 8]);
#pragma unroll
            for (int n = 0; n < 16; ++n) {
                uint32_t b0 = *reinterpret_cast<const uint32_t*>(&sB[(n * 8 + g) * SMSTRIDE + k0]);
                uint32_t b1 = *reinterpret_cast<const uint32_t*>(&sB[(n * 8 + g) * SMSTRIDE + k0 + 8]);
                mma_bf16(acc[n][0], acc[n][1], acc[n][2], acc[n][3], a0, a1, a2, a3, b0, b1);
            }
        }
        __syncthreads();
    }

    int r0l = warp * 16 + g;
    int r0 = mbase + r0l;
    int r1 = r0 + 8;
    float xq0 = g_xq[r0], xq1 = g_xq[r1];

    float mx0 = -1e30f, mx1 = -1e30f;
#pragma unroll
    for (int n = 0; n < 16; ++n) {
        int col = n * 8 + tg * 2;
        float cb0 = scb[col], cb1 = scb[col + 1];
        acc[n][0] += cb0; acc[n][1] += cb1;
        acc[n][2] += cb0; acc[n][3] += cb1;
        mx0 = fmaxf(mx0, fmaxf(acc[n][0], acc[n][1]));
        mx1 = fmaxf(mx1, fmaxf(acc[n][2], acc[n][3]));
    }
    mx0 = fmaxf(mx0, __shfl_xor_sync(0xffffffffu, mx0, 1));
    mx0 = fmaxf(mx0, __shfl_xor_sync(0xffffffffu, mx0, 2));
    mx1 = fmaxf(mx1, __shfl_xor_sync(0xffffffffu, mx1, 1));
    mx1 = fmaxf(mx1, __shfl_xor_sync(0xffffffffu, mx1, 2));

    // E fragment write, lane-major: [((l*32+btile)*16 + n)*32 + lane]
    int b = r0 & (BB - 1);
    int l = r0 >> 9;
    int btile = b >> 4;
    uint2* eout = &g_Efrag[((size_t)(l * 32 + btile) * 16) * 32 + lane];
#pragma unroll
    for (int n = 0; n < 16; ++n) {
        __nv_bfloat162 e01 = __floats2bfloat162_rn(fexp(acc[n][0] - mx0), fexp(acc[n][1] - mx0));
        __nv_bfloat162 e23 = __floats2bfloat162_rn(fexp(acc[n][2] - mx1), fexp(acc[n][3] - mx1));
        eout[n * 32] = make_uint2(pk(e01), pk(e23));
    }
    if (tg == 0) {
        g_dmaxT[(size_t)b * LL + l]       = mx0 + xq0;
        g_dmaxT[(size_t)(b + 8) * LL + l] = mx1 + xq1;
    }
}

// =====================================================================
// Kernel 4: forward recurrence — 16-warp n-split (1 ntile per warp).
// 32 CTAs x 512 threads: 4 warps/SMSP -> 4 independent HMMA chains in
// flight per scheduler (vs 2) to hide the 8-deep accumulate chain.
// Fragment logic identical to the proven R9 version.
// =====================================================================
#define ATSTRIDE 136
#define PSTRIDE  136

#define OFF_AT    0                          // 34816
#define OFF_P0    34816                      // 4352
#define OFF_P1    (OFF_P0 + 4352)            // 4352
#define OFF_DMAX  (OFF_P1 + 4352)            // 8192
#define OFF_MK    (OFF_DMAX + 8192)          // 2048
#define OFF_SRN   (OFF_MK + 2048)            // 16*16*4 = 1024
#define OFF_SSUM  (OFF_SRN + 1024)           // 1024
#define OFF_SM    (OFF_SSUM + 1024)          // 64
#define RECUR_SMEM (OFF_SM + 64)

__global__ __launch_bounds__(512) void recur_kernel(const float* __restrict__ masks) {
    extern __shared__ __align__(16) unsigned char dyn[];
    __nv_bfloat16* sAt = reinterpret_cast<__nv_bfloat16*>(dyn + OFF_AT);
    __nv_bfloat16* sp0 = reinterpret_cast<__nv_bfloat16*>(dyn + OFF_P0);
    __nv_bfloat16* sp1 = reinterpret_cast<__nv_bfloat16*>(dyn + OFF_P1);
    float* sdmax = reinterpret_cast<float*>(dyn + OFF_DMAX);
    unsigned char* smk = dyn + OFF_MK;
    float (*srn)[16]  = reinterpret_cast<float (*)[16]>(dyn + OFF_SRN);
    float (*ssum)[16] = reinterpret_cast<float (*)[16]>(dyn + OFF_SSUM);
    float* sM = reinterpret_cast<float*>(dyn + OFF_SM);

    int tid   = threadIdx.x;
    int lane  = tid & 31, w = tid >> 5;      // w in [0,16)
    int btile = blockIdx.x;
    int g = lane >> 2, tg = lane & 3;

    {
        const uint4* src = reinterpret_cast<const uint4*>(g_At);
        for (int idx = tid; idx < 2048; idx += 512) {
            int j = idx >> 4, c = idx & 15;
            *reinterpret_cast<uint4*>(&sAt[j * ATSTRIDE + c * 8]) = src[idx];
        }
    }
    for (int idx = tid; idx < 2048; idx += 512) {
        int bi = idx >> 7, l = idx & 127;
        sdmax[l * 16 + bi] = g_dmaxT[(size_t)(btile * 16 + bi) * LL + l];
        smk[l * 16 + bi]   = (masks[l * BB + btile * 16 + bi] >= 0.5f) ? 1 : 0;
    }
    __syncthreads();

    // B fragments for own ntile w: ldmx4 at np = w>>1, keep the (w&1) pair
    int q = lane >> 3, r = lane & 7;
    int rowb = ((q & 2) ? 8 : 0) + r;
    int kofs = (q & 1) ? 8 : 0;
    uint32_t bbase = smem_u32(&sAt[rowb * ATSTRIDE + kofs]);
    int np = w >> 1, h2 = w & 1;
    uint32_t bf[16];
#pragma unroll
    for (int kt = 0; kt < 8; ++kt) {
        uint32_t t0, t1, t2, t3;
        ldmx4(t0, t1, t2, t3, bbase + np * (16 * ATSTRIDE * 2) + kt * 32);
        bf[kt * 2 + 0] = h2 ? t2 : t0;
        bf[kt * 2 + 1] = h2 ? t3 : t1;
    }

    const uint2* __restrict__ Eb = g_Efrag + (size_t)btile * 512 + lane;

    uint32_t pv01, pv23;
    {
        uint2 e = Eb[w * 32];
        pv01 = e.x;
        pv23 = e.y;
    }
    {
        int col = w * 8 + 2 * tg;
        *reinterpret_cast<uint32_t*>(&sp0[g * PSTRIDE + col])       = pv01;
        *reinterpret_cast<uint32_t*>(&sp0[(g + 8) * PSTRIDE + col]) = pv23;
    }
    float Mg = LOGPI_INIT + sdmax[g];
    float Mh = LOGPI_INIT + sdmax[g + 8];
    __syncthreads();

    int arow = (lane & 7) + ((lane & 8) ? 8 : 0);
    int akof = (lane & 16) ? 8 : 0;
    uint32_t abase[2];
    abase[0] = smem_u32(&sp0[arow * PSTRIDE + akof]);
    abase[1] = smem_u32(&sp1[arow * PSTRIDE + akof]);

    int buf = 0;
    for (int l = 1; l < LL; ++l) {
        uint32_t af[32];
#pragma unroll
        for (int kt = 0; kt < 8; ++kt)
            ldmx4(af[kt * 4 + 0], af[kt * 4 + 1], af[kt * 4 + 2], af[kt * 4 + 3],
                  abase[buf] + kt * 32);

        uint2 ef = Eb[(size_t)l * 16384 + w * 32];

        float dm0 = sdmax[l * 16 + g];
        float dm1 = sdmax[l * 16 + g + 8];
        int mk0 = smk[l * 16 + g];
        int mk1 = smk[l * 16 + g + 8];

        float acc[4];
        acc[0] = acc[1] = acc[2] = acc[3] = 0.f;

        // 8 HMMA: 8 k-tiles x own ntile
#pragma unroll
        for (int kt = 0; kt < 8; ++kt) {
            mma_bf16(acc[0], acc[1], acc[2], acc[3],
                     af[kt * 4 + 0], af[kt * 4 + 1], af[kt * 4 + 2], af[kt * 4 + 3],
                     bf[kt * 2 + 0], bf[kt * 2 + 1]);
        }

        // epilogue: * E, mask blend (packed select)
        {
            float2 eg = __bfloat1622float2(upk(ef.x));
            float2 eh = __bfloat1622float2(upk(ef.y));
            uint32_t u01 = pk(__floats2bfloat162_rn(acc[0] * eg.x, acc[1] * eg.y));
            uint32_t u23 = pk(__floats2bfloat162_rn(acc[2] * eh.x, acc[3] * eh.y));
            if (!mk0) u01 = pv01;
            if (!mk1) u23 = pv23;
            pv01 = u01;
            pv23 = u23;
        }
        if (mk0) Mg += dm0;
        if (mk1) Mh += dm1;

        // periodic renorm (cross-warp max -> fold into M)
        if ((l & 7) == 0) {
            float2 v01 = __bfloat1622float2(upk(pv01));
            float2 v23 = __bfloat1622float2(upk(pv23));
            float mg = fmaxf(1e-30f, fmaxf(v01.x, v01.y));
            float mh = fmaxf(1e-30f, fmaxf(v23.x, v23.y));
            mg = fmaxf(mg, __shfl_xor_sync(0xffffffffu, mg, 1));
            mg = fmaxf(mg, __shfl_xor_sync(0xffffffffu, mg, 2));
            mh = fmaxf(mh, __shfl_xor_sync(0xffffffffu, mh, 1));
            mh = fmaxf(mh, __shfl_xor_sync(0xffffffffu, mh, 2));
            if (tg == 0) { srn[w][g] = mg; srn[w][g + 8] = mh; }
            __syncthreads();
#pragma unroll
            for (int ww = 0; ww < 16; ++ww) {
                mg = fmaxf(mg, srn[ww][g]);
                mh = fmaxf(mh, srn[ww][g + 8]);
            }
            float rg = 1.f / mg, rh = 1.f / mh;
            v01 = __bfloat1622float2(upk(pv01));
            v23 = __bfloat1622float2(upk(pv23));
            pv01 = pk(__floats2bfloat162_rn(v01.x * rg, v01.y * rg));
            pv23 = pk(__floats2bfloat162_rn(v23.x * rh, v23.y * rh));
            Mg += __logf(mg);
            Mh += __logf(mh);
        }

        // store own slice to the other buffer, then one barrier
        int nbuf = buf ^ 1;
        {
            __nv_bfloat16* base = nbuf ? sp1 : sp0;
            int col = w * 8 + 2 * tg;
            *reinterpret_cast<uint32_t*>(&base[g * PSTRIDE + col])       = pv01;
            *reinterpret_cast<uint32_t*>(&base[(g + 8) * PSTRIDE + col]) = pv23;
        }
        __syncthreads();
        buf = nbuf;
    }

    // objective per batch: M + log(sum_j p_j); combine across warps
    float2 v01 = __bfloat1622float2(upk(pv01));
    float2 v23 = __bfloat1622float2(upk(pv23));
    float Sg = v01.x + v01.y;
    float Sh = v23.x + v23.y;
    Sg += __shfl_xor_sync(0xffffffffu, Sg, 1);
    Sg += __shfl_xor_sync(0xffffffffu, Sg, 2);
    Sh += __shfl_xor_sync(0xffffffffu, Sh, 1);
    Sh += __shfl_xor_sync(0xffffffffu, Sh, 2);
    if (tg == 0) {
        ssum[w][g] = Sg;
        ssum[w][g + 8] = Sh;
        if (w == 0) { sM[g] = Mg; sM[g + 8] = Mh; }
    }
    __syncthreads();
    if (tid < 16) {
        float S = 0.f;
#pragma unroll
        for (int ww = 0; ww < 16; ++ww) S += ssum[ww][tid];
        S = fmaxf(S, 1e-37f);
        g_perb[btile * 16 + tid] = sM[tid] + __logf(S);
    }
}

// =====================================================================
// Kernel 5: deterministic final reduction over 512 batch rows
// =====================================================================
__global__ void finalize_kernel(float* __restrict__ out, int out_size) {
    __shared__ float s[256];
    int t = threadIdx.x;
    s[t] = g_perb[t] + g_perb[t + 256];
    __syncthreads();
    for (int off = 128; off > 0; off >>= 1) {
        if (t < off) s[t] += s[t + off];
        __syncthreads();
    }
    for (int i = t; i < out_size; i += 256)
        if (i != 0) out[i] = 0.f;   // jacobian_loss = 0
    if (t == 0) out[0] = s[0];
}

// =====================================================================
extern "C" void kernel_launch(void* const* d_in, const int* in_sizes, int n_in,
                              void* d_out, int out_size) {
    const float* sents   = (const float*)d_in[0];
    const float* masks   = (const float*)d_in[1];
    const float* tparams = (const float*)d_in[2];
    const float* means   = (const float*)d_in[3];
    const float* var     = (const float*)d_in[4];
    float* out = (float*)d_out;

    cudaFuncSetAttribute(recur_kernel, cudaFuncAttributeMaxDynamicSharedMemorySize, RECUR_SMEM);

    prep_kernel<<<1, 512>>>(tparams, means, var);
    xqcast_kernel<<<LB / 8, 256>>>(sents);
    density_kernel<<<LB / 128, 256>>>();
    recur_kernel<<<32, 512, RECUR_SMEM>>>(masks);
    finalize_kernel<<<1, 256>>>(out, out_size);
}

// round 13
// speedup vs baseline: 1.1479x; 1.1356x over previous
#include <cuda_runtime.h>
#include <cuda_bf16.h>
#include <cstdint>
#include <math.h>

// Problem constants
#define LL 128
#define BB 512
#define DD 512
#define SS 128
#define LB (LL * BB)   // 65536

// -------- device scratch --------
__device__ __align__(16) float          g_colbias[SS];
__device__ __align__(16) float          g_rvar[DD];
__device__ __align__(16) float          g_xq[LB];               // -0.5*sum x^2/var
__device__ __align__(16) __nv_bfloat16  g_Xs[(size_t)LB * DD];  // X in bf16 (64 MB)
__device__ __align__(16) __nv_bfloat16  g_Mv[SS * DD];          // mu/var bf16, [s][d]
__device__ __align__(16) __nv_bfloat16  g_At[SS * SS];          // A^T bf16
// E in mma-fragment layout, lane-major: [((l*32 + btile)*16 + n)*32 + lane]
__device__ __align__(16) uint2          g_Efrag[(size_t)LL * 32 * 16 * 32]; // 16 MB
__device__ __align__(16) float          g_dmaxT[BB * LL];       // dmax transposed: [b][l]
__device__ __align__(16) float          g_perb[BB];

#define LOG2PI 1.8378770664093453f
#define LOGPI_INIT (-4.852030263919617f)   // -log(128)

// ---- fast exp on the FMA pipe (x <= 0 expected; flushes below -80) ----
__device__ __forceinline__ float fexp(float x) {
    float t = fmaf(x, 1.4426950408889634f, 12582912.0f);
    int   ni = __float_as_int(t) - 0x4B400000;
    float n  = t - 12582912.0f;
    float f  = fmaf(x, 1.4426950408889634f, -n);
    float r  = 0.0013333558f;
    r = fmaf(r, f, 0.0096181291f);
    r = fmaf(r, f, 0.0555041087f);
    r = fmaf(r, f, 0.2402264689f);
    r = fmaf(r, f, 0.6931471806f);
    r = fmaf(r, f, 1.0f);
    float res = __int_as_float(__float_as_int(r) + (ni << 23));
    return (x > -80.0f) ? res : 0.0f;
}

__device__ __forceinline__ uint32_t pk(__nv_bfloat162 v) { return *reinterpret_cast<uint32_t*>(&v); }
__device__ __forceinline__ __nv_bfloat162 upk(uint32_t v) { return *reinterpret_cast<__nv_bfloat162*>(&v); }
__device__ __forceinline__ uint32_t smem_u32(const void* p) {
    return (uint32_t)__cvta_generic_to_shared(p);
}

__device__ __forceinline__ void mma_bf16(float& c0, float& c1, float& c2, float& c3,
                                         uint32_t a0, uint32_t a1, uint32_t a2, uint32_t a3,
                                         uint32_t b0, uint32_t b1) {
    asm volatile(
        "mma.sync.aligned.m16n8k16.row.col.f32.bf16.bf16.f32 "
        "{%0,%1,%2,%3}, {%4,%5,%6,%7}, {%8,%9}, {%0,%1,%2,%3};\n"
        : "+f"(c0), "+f"(c1), "+f"(c2), "+f"(c3)
        : "r"(a0), "r"(a1), "r"(a2), "r"(a3), "r"(b0), "r"(b1));
}

__device__ __forceinline__ void ldmx4(uint32_t& r0, uint32_t& r1, uint32_t& r2, uint32_t& r3,
                                      uint32_t addr) {
    asm volatile("ldmatrix.sync.aligned.m8n8.x4.shared.b16 {%0,%1,%2,%3}, [%4];"
                 : "=r"(r0), "=r"(r1), "=r"(r2), "=r"(r3) : "r"(addr));
}

// =====================================================================
// Kernel 1: preprocessing (1 block, 512 threads)
// =====================================================================
__global__ void prep_kernel(const float* __restrict__ tparams,
                            const float* __restrict__ means,
                            const float* __restrict__ var) {
    __shared__ float sred[512];
    int t = threadIdx.x;

    float v = var[t];
    g_rvar[t] = 1.0f / v;
    sred[t] = logf(v);
    __syncthreads();
    for (int off = 256; off > 0; off >>= 1) {
        if (t < off) sred[t] += sred[t + off];
        __syncthreads();
    }
    float slv = sred[0];
    float c = -256.0f * LOG2PI - 0.5f * slv;

    int q   = t & 3;      // 0..3
    int grp = t >> 2;     // 0..127  (row i)

    // col bias
    {
        float mq = 0.f;
        for (int d = q; d < DD; d += 4) {
            float m = means[grp * DD + d];
            mq += m * m * g_rvar[d];
        }
        mq += __shfl_xor_sync(0xffffffffu, mq, 1);
        mq += __shfl_xor_sync(0xffffffffu, mq, 2);
        if (q == 0) g_colbias[grp] = c - 0.5f * mq;
    }

    // At[j][i] = exp(tparams[i][j] - lse_j'(tparams[i][:]))
    {
        float mx = -1e30f;
        for (int jj = q; jj < SS; jj += 4) mx = fmaxf(mx, tparams[grp * SS + jj]);
        mx = fmaxf(mx, __shfl_xor_sync(0xffffffffu, mx, 1));
        mx = fmaxf(mx, __shfl_xor_sync(0xffffffffu, mx, 2));
        float se = 0.f;
        for (int jj = q; jj < SS; jj += 4) se += __expf(tparams[grp * SS + jj] - mx);
        se += __shfl_xor_sync(0xffffffffu, se, 1);
        se += __shfl_xor_sync(0xffffffffu, se, 2);
        float lse = mx + __logf(se);
        for (int jj = q; jj < SS; jj += 4)
            g_At[jj * SS + grp] = __float2bfloat16(__expf(tparams[grp * SS + jj] - lse));
    }

    // Mv = mu / var in bf16
    for (int idx = t; idx < SS * DD; idx += 512) {
        int d = idx & (DD - 1);
        g_Mv[idx] = __float2bfloat16(means[idx] * g_rvar[d]);
    }
}

// =====================================================================
// Kernel 2: per-row -0.5*sum(x^2/var) + bf16 cast of X (DRAM-bound)
// =====================================================================
__global__ __launch_bounds__(256) void xqcast_kernel(const float* __restrict__ sents) {
    __shared__ __align__(16) float srv[DD];
    int tid = threadIdx.x;
    for (int i = tid; i < DD; i += 256) srv[i] = g_rvar[i];
    __syncthreads();

    int warp = tid >> 5, lane = tid & 31;
    int row = blockIdx.x * 8 + warp;

    const float4* src = reinterpret_cast<const float4*>(sents + (size_t)row * DD);
    float sum = 0.f;
#pragma unroll
    for (int c = 0; c < 4; ++c) {
        int idx4 = c * 32 + lane;   // float4 index in row (128 per row)
        float4 x  = src[idx4];
        float4 rv = *reinterpret_cast<const float4*>(&srv[idx4 * 4]);
        sum += x.x * x.x * rv.x + x.y * x.y * rv.y + x.z * x.z * rv.z + x.w * x.w * rv.w;
        __nv_bfloat162 p0 = __float22bfloat162_rn(make_float2(x.x, x.y));
        __nv_bfloat162 p1 = __float22bfloat162_rn(make_float2(x.z, x.w));
        __nv_bfloat162* dst = reinterpret_cast<__nv_bfloat162*>(&g_Xs[(size_t)row * DD + idx4 * 4]);
        dst[0] = p0;
        dst[1] = p1;
    }
#pragma unroll
    for (int off = 16; off > 0; off >>= 1)
        sum += __shfl_xor_sync(0xffffffffu, sum, off);
    if (lane == 0) g_xq[row] = -0.5f * sum;
}

// =====================================================================
// Kernel 3: density GEMM — 2D warp tiling (4m x 2n), full ldmatrix.
// Each warp: m32 x n64 (2 m-tiles x 8 n-tiles). sB redundancy 8x -> 4x.
// =====================================================================
#define SMSTRIDE 72

__global__ __launch_bounds__(256) void density_kernel() {
    __shared__ __align__(16) __nv_bfloat16 sA[128 * SMSTRIDE];
    __shared__ __align__(16) __nv_bfloat16 sB[128 * SMSTRIDE];
    __shared__ float scb[128];
    __shared__ float sMX[2][128];

    int tid  = threadIdx.x;
    int warp = tid >> 5, lane = tid & 31;
    int g = lane >> 2, tg = lane & 3;
    int warp_m = warp >> 1, warp_n = warp & 1;
    int mbase = blockIdx.x * 128;

    if (tid < 128) scb[tid] = g_colbias[tid];

    // a-side ldmatrix lane mapping (proven in recur): a0=rows0-7 klow, a1=rows8-15 klow,
    // a2=rows0-7 khigh, a3=rows8-15 khigh
    int arow = (lane & 7) + ((lane & 8) ? 8 : 0);
    int akof = (lane & 16) ? 8 : 0;
    // b-side mapping: t0,t1 = n-tile(rows0-7) b0,b1; t2,t3 = n-tile(rows8-15)
    int q = lane >> 3, r = lane & 7;
    int rowb = ((q & 2) ? 8 : 0) + r;
    int kofs = (q & 1) ? 8 : 0;

    uint32_t sa_base = smem_u32(sA);
    uint32_t sb_base = smem_u32(sB);

    float acc[2][8][4];
#pragma unroll
    for (int mt = 0; mt < 2; ++mt)
#pragma unroll
        for (int n = 0; n < 8; ++n)
#pragma unroll
            for (int k = 0; k < 4; ++k) acc[mt][n][k] = 0.f;

    __syncthreads();

    for (int ko = 0; ko < 8; ++ko) {
#pragma unroll
        for (int k = 0; k < 4; ++k) {
            int idx = tid + k * 256;         // 1024 uint4 total
            int rr = idx >> 3, c8 = idx & 7;
            uint4 va = *reinterpret_cast<const uint4*>(&g_Xs[(size_t)(mbase + rr) * DD + ko * 64 + c8 * 8]);
            *reinterpret_cast<uint4*>(&sA[rr * SMSTRIDE + c8 * 8]) = va;
        }
#pragma unroll
        for (int k = 0; k < 4; ++k) {
            int idx = tid + k * 256;
            int rr = idx >> 3, c8 = idx & 7;
            uint4 vb = *reinterpret_cast<const uint4*>(&g_Mv[(size_t)rr * DD + ko * 64 + c8 * 8]);
            *reinterpret_cast<uint4*>(&sB[rr * SMSTRIDE + c8 * 8]) = vb;
        }
        __syncthreads();

#pragma unroll
        for (int ks = 0; ks < 4; ++ks) {
            int kb = ks * 16;
            uint32_t afr[2][4];
#pragma unroll
            for (int mt = 0; mt < 2; ++mt)
                ldmx4(afr[mt][0], afr[mt][1], afr[mt][2], afr[mt][3],
                      sa_base + ((warp_m * 32 + mt * 16 + arow) * SMSTRIDE + kb + akof) * 2);
#pragma unroll
            for (int npair = 0; npair < 4; ++npair) {
                uint32_t t0, t1, t2, t3;
                ldmx4(t0, t1, t2, t3,
                      sb_base + ((warp_n * 64 + npair * 16 + rowb) * SMSTRIDE + kb + kofs) * 2);
#pragma unroll
                for (int mt = 0; mt < 2; ++mt) {
                    mma_bf16(acc[mt][2 * npair][0], acc[mt][2 * npair][1],
                             acc[mt][2 * npair][2], acc[mt][2 * npair][3],
                             afr[mt][0], afr[mt][1], afr[mt][2], afr[mt][3], t0, t1);
                    mma_bf16(acc[mt][2 * npair + 1][0], acc[mt][2 * npair + 1][1],
                             acc[mt][2 * npair + 1][2], acc[mt][2 * npair + 1][3],
                             afr[mt][0], afr[mt][1], afr[mt][2], afr[mt][3], t2, t3);
                }
            }
        }
        __syncthreads();
    }

    // colbias + per-(mt,row) partial max over own n-half
    float mx[2][2];
    mx[0][0] = mx[0][1] = mx[1][0] = mx[1][1] = -1e30f;
#pragma unroll
    for (int mt = 0; mt < 2; ++mt)
#pragma unroll
        for (int n = 0; n < 8; ++n) {
            int cglob = (warp_n * 8 + n) * 8 + tg * 2;
            float cb0 = scb[cglob], cb1 = scb[cglob + 1];
            acc[mt][n][0] += cb0; acc[mt][n][1] += cb1;
            acc[mt][n][2] += cb0; acc[mt][n][3] += cb1;
            mx[mt][0] = fmaxf(mx[mt][0], fmaxf(acc[mt][n][0], acc[mt][n][1]));
            mx[mt][1] = fmaxf(mx[mt][1], fmaxf(acc[mt][n][2], acc[mt][n][3]));
        }
#pragma unroll
    for (int mt = 0; mt < 2; ++mt)
#pragma unroll
        for (int h = 0; h < 2; ++h) {
            mx[mt][h] = fmaxf(mx[mt][h], __shfl_xor_sync(0xffffffffu, mx[mt][h], 1));
            mx[mt][h] = fmaxf(mx[mt][h], __shfl_xor_sync(0xffffffffu, mx[mt][h], 2));
        }
    if (tg == 0) {
#pragma unroll
        for (int mt = 0; mt < 2; ++mt) {
            int rbase = warp_m * 32 + mt * 16;
            sMX[warp_n][rbase + g]     = mx[mt][0];
            sMX[warp_n][rbase + g + 8] = mx[mt][1];
        }
    }
    __syncthreads();

#pragma unroll
    for (int mt = 0; mt < 2; ++mt) {
        int rbase = warp_m * 32 + mt * 16;
        float fmx0 = fmaxf(sMX[0][rbase + g], sMX[1][rbase + g]);
        float fmx1 = fmaxf(sMX[0][rbase + g + 8], sMX[1][rbase + g + 8]);

        int r0 = mbase + rbase + g;           // global row for lane row g
        int b = r0 & (BB - 1);
        int l = r0 >> 9;
        int btile = b >> 4;
        uint2* eout = &g_Efrag[((size_t)(l * 32 + btile) * 16 + warp_n * 8) * 32 + lane];
#pragma unroll
        for (int n = 0; n < 8; ++n) {
            __nv_bfloat162 e01 = __floats2bfloat162_rn(fexp(acc[mt][n][0] - fmx0),
                                                       fexp(acc[mt][n][1] - fmx0));
            __nv_bfloat162 e23 = __floats2bfloat162_rn(fexp(acc[mt][n][2] - fmx1),
                                                       fexp(acc[mt][n][3] - fmx1));
            eout[n * 32] = make_uint2(pk(e01), pk(e23));
        }
        if (warp_n == 0 && tg == 0) {
            g_dmaxT[(size_t)b * LL + l]       = fmx0 + g_xq[r0];
            g_dmaxT[(size_t)(b + 8) * LL + l] = fmx1 + g_xq[r0 + 8];
        }
    }
}

// =====================================================================
// Kernel 4: forward recurrence — 8-warp n-split (R9-proven, 91.3us).
// =====================================================================
#define ATSTRIDE 136
#define PSTRIDE  136

#define OFF_AT    0
#define OFF_P0    34816
#define OFF_P1    (OFF_P0 + 4352)
#define OFF_DMAX  (OFF_P1 + 4352)
#define OFF_MK    (OFF_DMAX + 8192)
#define OFF_SRN   (OFF_MK + 2048)
#define OFF_SSUM  (OFF_SRN + 512)
#define OFF_SM    (OFF_SSUM + 512)
#define RECUR_SMEM (OFF_SM + 64)

__global__ __launch_bounds__(256) void recur_kernel(const float* __restrict__ masks) {
    extern __shared__ __align__(16) unsigned char dyn[];
    __nv_bfloat16* sAt = reinterpret_cast<__nv_bfloat16*>(dyn + OFF_AT);
    __nv_bfloat16* sp0 = reinterpret_cast<__nv_bfloat16*>(dyn + OFF_P0);
    __nv_bfloat16* sp1 = reinterpret_cast<__nv_bfloat16*>(dyn + OFF_P1);
    float* sdmax = reinterpret_cast<float*>(dyn + OFF_DMAX);
    unsigned char* smk = dyn + OFF_MK;
    float (*srn)[16]  = reinterpret_cast<float (*)[16]>(dyn + OFF_SRN);
    float (*ssum)[16] = reinterpret_cast<float (*)[16]>(dyn + OFF_SSUM);
    float* sM = reinterpret_cast<float*>(dyn + OFF_SM);

    int tid   = threadIdx.x;
    int lane  = tid & 31, w = tid >> 5;     // w in [0,8)
    int btile = blockIdx.x;                  // 0..31
    int g = lane >> 2, tg = lane & 3;

    {
        const uint4* src = reinterpret_cast<const uint4*>(g_At);
        for (int idx = tid; idx < 2048; idx += 256) {
            int j = idx >> 4, c = idx & 15;
            *reinterpret_cast<uint4*>(&sAt[j * ATSTRIDE + c * 8]) = src[idx];
        }
    }
    for (int idx = tid; idx < 2048; idx += 256) {
        int bi = idx >> 7, l = idx & 127;
        sdmax[l * 16 + bi] = g_dmaxT[(size_t)(btile * 16 + bi) * LL + l];
        smk[l * 16 + bi]   = (masks[l * BB + btile * 16 + bi] >= 0.5f) ? 1 : 0;
    }
    __syncthreads();

    // hoist B fragments: warp w covers n-pair group np = w
    int q = lane >> 3, r = lane & 7;
    int rowb = ((q & 2) ? 8 : 0) + r;
    int kofs = (q & 1) ? 8 : 0;
    uint32_t bbase = smem_u32(&sAt[rowb * ATSTRIDE + kofs]);
    uint32_t bf[32];
#pragma unroll
    for (int kt = 0; kt < 8; ++kt) {
        ldmx4(bf[kt * 4 + 0], bf[kt * 4 + 1], bf[kt * 4 + 2], bf[kt * 4 + 3],
              bbase + w * (16 * ATSTRIDE * 2) + kt * 32);
    }

    const uint2* __restrict__ Eb = g_Efrag + (size_t)btile * 512 + lane;

    uint32_t pv01[2], pv23[2];
#pragma unroll
    for (int lt = 0; lt < 2; ++lt) {
        uint2 e = Eb[(2 * w + lt) * 32];
        pv01[lt] = e.x;
        pv23[lt] = e.y;
    }
#pragma unroll
    for (int lt = 0; lt < 2; ++lt) {
        int col = (2 * w + lt) * 8 + 2 * tg;
        *reinterpret_cast<uint32_t*>(&sp0[g * PSTRIDE + col])       = pv01[lt];
        *reinterpret_cast<uint32_t*>(&sp0[(g + 8) * PSTRIDE + col]) = pv23[lt];
    }
    float Mg = LOGPI_INIT + sdmax[g];
    float Mh = LOGPI_INIT + sdmax[g + 8];
    __syncthreads();

    int arow = (lane & 7) + ((lane & 8) ? 8 : 0);
    int akof = (lane & 16) ? 8 : 0;
    uint32_t abase[2];
    abase[0] = smem_u32(&sp0[arow * PSTRIDE + akof]);
    abase[1] = smem_u32(&sp1[arow * PSTRIDE + akof]);

    int buf = 0;
    for (int l = 1; l < LL; ++l) {
        uint32_t af[32];
#pragma unroll
        for (int kt = 0; kt < 8; ++kt)
            ldmx4(af[kt * 4 + 0], af[kt * 4 + 1], af[kt * 4 + 2], af[kt * 4 + 3],
                  abase[buf] + kt * 32);

        const uint2* Ep = Eb + (size_t)l * 16384;
        uint2 ef[2];
#pragma unroll
        for (int lt = 0; lt < 2; ++lt) ef[lt] = Ep[(2 * w + lt) * 32];

        float dm0 = sdmax[l * 16 + g];
        float dm1 = sdmax[l * 16 + g + 8];
        int mk0 = smk[l * 16 + g];
        int mk1 = smk[l * 16 + g + 8];

        float acc[2][4];
#pragma unroll
        for (int n = 0; n < 2; ++n)
#pragma unroll
            for (int k = 0; k < 4; ++k) acc[n][k] = 0.f;

#pragma unroll
        for (int kt = 0; kt < 8; ++kt) {
            uint32_t a0 = af[kt * 4 + 0], a1 = af[kt * 4 + 1];
            uint32_t a2 = af[kt * 4 + 2], a3 = af[kt * 4 + 3];
            const uint32_t* bb = &bf[kt * 4];
            mma_bf16(acc[0][0], acc[0][1], acc[0][2], acc[0][3],
                     a0, a1, a2, a3, bb[0], bb[1]);
            mma_bf16(acc[1][0], acc[1][1], acc[1][2], acc[1][3],
                     a0, a1, a2, a3, bb[2], bb[3]);
        }

#pragma unroll
        for (int lt = 0; lt < 2; ++lt) {
            float2 eg = __bfloat1622float2(upk(ef[lt].x));
            float2 eh = __bfloat1622float2(upk(ef[lt].y));
            uint32_t u01 = pk(__floats2bfloat162_rn(acc[lt][0] * eg.x, acc[lt][1] * eg.y));
            uint32_t u23 = pk(__floats2bfloat162_rn(acc[lt][2] * eh.x, acc[lt][3] * eh.y));
            if (!mk0) u01 = pv01[lt];
            if (!mk1) u23 = pv23[lt];
            pv01[lt] = u01;
            pv23[lt] = u23;
        }
        if (mk0) Mg += dm0;
        if (mk1) Mh += dm1;

        if ((l & 7) == 0) {
            float mg = 1e-30f, mh = 1e-30f;
#pragma unroll
            for (int lt = 0; lt < 2; ++lt) {
                float2 v01 = __bfloat1622float2(upk(pv01[lt]));
                float2 v23 = __bfloat1622float2(upk(pv23[lt]));
                mg = fmaxf(mg, fmaxf(v01.x, v01.y));
                mh = fmaxf(mh, fmaxf(v23.x, v23.y));
            }
            mg = fmaxf(mg, __shfl_xor_sync(0xffffffffu, mg, 1));
            mg = fmaxf(mg, __shfl_xor_sync(0xffffffffu, mg, 2));
            mh = fmaxf(mh, __shfl_xor_sync(0xffffffffu, mh, 1));
            mh = fmaxf(mh, __shfl_xor_sync(0xffffffffu, mh, 2));
            if (tg == 0) { srn[w][g] = mg; srn[w][g + 8] = mh; }
            __syncthreads();
#pragma unroll
            for (int ww = 0; ww < 8; ++ww) {
                mg = fmaxf(mg, srn[ww][g]);
                mh = fmaxf(mh, srn[ww][g + 8]);
            }
            float rg = 1.f / mg, rh = 1.f / mh;
#pragma unroll
            for (int lt = 0; lt < 2; ++lt) {
                float2 v01 = __bfloat1622float2(upk(pv01[lt]));
                float2 v23 = __bfloat1622float2(upk(pv23[lt]));
                pv01[lt] = pk(__floats2bfloat162_rn(v01.x * rg, v01.y * rg));
                pv23[lt] = pk(__floats2bfloat162_rn(v23.x * rh, v23.y * rh));
            }
            Mg += __logf(mg);
            Mh += __logf(mh);
        }

        int nbuf = buf ^ 1;
        {
            __nv_bfloat16* base = nbuf ? sp1 : sp0;
#pragma unroll
            for (int lt = 0; lt < 2; ++lt) {
                int col = (2 * w + lt) * 8 + 2 * tg;
                *reinterpret_cast<uint32_t*>(&base[g * PSTRIDE + col])       = pv01[lt];
                *reinterpret_cast<uint32_t*>(&base[(g + 8) * PSTRIDE + col]) = pv23[lt];
            }
        }
        __syncthreads();
        buf = nbuf;
    }

    float Sg = 0.f, Sh = 0.f;
#pragma unroll
    for (int lt = 0; lt < 2; ++lt) {
        float2 v01 = __bfloat1622float2(upk(pv01[lt]));
        float2 v23 = __bfloat1622float2(upk(pv23[lt]));
        Sg += v01.x + v01.y;
        Sh += v23.x + v23.y;
    }
    Sg += __shfl_xor_sync(0xffffffffu, Sg, 1);
    Sg += __shfl_xor_sync(0xffffffffu, Sg, 2);
    Sh += __shfl_xor_sync(0xffffffffu, Sh, 1);
    Sh += __shfl_xor_sync(0xffffffffu, Sh, 2);
    if (tg == 0) {
        ssum[w][g] = Sg;
        ssum[w][g + 8] = Sh;
        if (w == 0) { sM[g] = Mg; sM[g + 8] = Mh; }
    }
    __syncthreads();
    if (tid < 16) {
        float S = 0.f;
#pragma unroll
        for (int ww = 0; ww < 8; ++ww) S += ssum[ww][tid];
        S = fmaxf(S, 1e-37f);
        g_perb[btile * 16 + tid] = sM[tid] + __logf(S);
    }
}

// =====================================================================
// Kernel 5: deterministic final reduction over 512 batch rows
// =====================================================================
__global__ void finalize_kernel(float* __restrict__ out, int out_size) {
    __shared__ float s[256];
    int t = threadIdx.x;
    s[t] = g_perb[t] + g_perb[t + 256];
    __syncthreads();
    for (int off = 128; off > 0; off >>= 1) {
        if (t < off) s[t] += s[t + off];
        __syncthreads();
    }
    for (int i = t; i < out_size; i += 256)
        if (i != 0) out[i] = 0.f;   // jacobian_loss = 0
    if (t == 0) out[0] = s[0];
}

// =====================================================================
extern "C" void kernel_launch(void* const* d_in, const int* in_sizes, int n_in,
                              void* d_out, int out_size) {
    const float* sents   = (const float*)d_in[0];
    const float* masks   = (const float*)d_in[1];
    const float* tparams = (const float*)d_in[2];
    const float* means   = (const float*)d_in[3];
    const float* var     = (const float*)d_in[4];
    float* out = (float*)d_out;

    cudaFuncSetAttribute(recur_kernel, cudaFuncAttributeMaxDynamicSharedMemorySize, RECUR_SMEM);

    prep_kernel<<<1, 512>>>(tparams, means, var);
    xqcast_kernel<<<LB / 8, 256>>>(sents);
    density_kernel<<<LB / 128, 256>>>();
    recur_kernel<<<32, 256, RECUR_SMEM>>>(masks);
    finalize_kernel<<<1, 256>>>(out, out_size);
}

// round 15
// speedup vs baseline: 1.2122x; 1.0560x over previous
#include <cuda_runtime.h>
#include <cuda_bf16.h>
#include <cstdint>
#include <math.h>

// Problem constants
#define LL 128
#define BB 512
#define DD 512
#define SS 128
#define LB (LL * BB)   // 65536

// -------- device scratch --------
__device__ __align__(16) float          g_colbias[SS];
__device__ __align__(16) float          g_rvar[DD];
__device__ __align__(16) float          g_xq[LB];               // -0.5*sum x^2/var
__device__ __align__(16) __nv_bfloat16  g_Xs[(size_t)LB * DD];  // X in bf16 (64 MB)
__device__ __align__(16) __nv_bfloat16  g_Mv[SS * DD];          // mu/var bf16, [s][d]
__device__ __align__(16) __nv_bfloat16  g_At[SS * SS];          // A^T bf16, [j][i]
// E bf16, layout [l][b>>3][j][b&7]  (16 MB)
__device__ __align__(16) __nv_bfloat16  g_E[(size_t)LL * 64 * 128 * 8];
__device__ __align__(16) float          g_dmaxT[BB * LL];       // dmax transposed: [b][l]
__device__ __align__(16) float          g_perb[BB];

#define LOG2PI 1.8378770664093453f
#define LOGPI_INIT (-4.852030263919617f)   // -log(128)

// ---- fast exp on the FMA pipe (x <= 0 expected; flushes below -80) ----
__device__ __forceinline__ float fexp(float x) {
    float t = fmaf(x, 1.4426950408889634f, 12582912.0f);
    int   ni = __float_as_int(t) - 0x4B400000;
    float n  = t - 12582912.0f;
    float f  = fmaf(x, 1.4426950408889634f, -n);
    float r  = 0.0013333558f;
    r = fmaf(r, f, 0.0096181291f);
    r = fmaf(r, f, 0.0555041087f);
    r = fmaf(r, f, 0.2402264689f);
    r = fmaf(r, f, 0.6931471806f);
    r = fmaf(r, f, 1.0f);
    float res = __int_as_float(__float_as_int(r) + (ni << 23));
    return (x > -80.0f) ? res : 0.0f;
}

__device__ __forceinline__ uint32_t pk(__nv_bfloat162 v) { return *reinterpret_cast<uint32_t*>(&v); }
__device__ __forceinline__ __nv_bfloat162 upk(uint32_t v) { return *reinterpret_cast<__nv_bfloat162*>(&v); }
__device__ __forceinline__ uint32_t smem_u32(const void* p) {
    return (uint32_t)__cvta_generic_to_shared(p);
}

__device__ __forceinline__ void mma_bf16(float& c0, float& c1, float& c2, float& c3,
                                         uint32_t a0, uint32_t a1, uint32_t a2, uint32_t a3,
                                         uint32_t b0, uint32_t b1) {
    asm volatile(
        "mma.sync.aligned.m16n8k16.row.col.f32.bf16.bf16.f32 "
        "{%0,%1,%2,%3}, {%4,%5,%6,%7}, {%8,%9}, {%0,%1,%2,%3};\n"
        : "+f"(c0), "+f"(c1), "+f"(c2), "+f"(c3)
        : "r"(a0), "r"(a1), "r"(a2), "r"(a3), "r"(b0), "r"(b1));
}

__device__ __forceinline__ void ldmx4(uint32_t& r0, uint32_t& r1, uint32_t& r2, uint32_t& r3,
                                      uint32_t addr) {
    asm volatile("ldmatrix.sync.aligned.m8n8.x4.shared.b16 {%0,%1,%2,%3}, [%4];"
                 : "=r"(r0), "=r"(r1), "=r"(r2), "=r"(r3) : "r"(addr));
}

// =====================================================================
// Kernel 1: preprocessing (1 block, 512 threads)
// =====================================================================
__global__ void prep_kernel(const float* __restrict__ tparams,
                            const float* __restrict__ means,
                            const float* __restrict__ var) {
    __shared__ float sred[512];
    int t = threadIdx.x;

    float v = var[t];
    g_rvar[t] = 1.0f / v;
    sred[t] = logf(v);
    __syncthreads();
    for (int off = 256; off > 0; off >>= 1) {
        if (t < off) sred[t] += sred[t + off];
        __syncthreads();
    }
    float slv = sred[0];
    float c = -256.0f * LOG2PI - 0.5f * slv;

    int q   = t & 3;      // 0..3
    int grp = t >> 2;     // 0..127  (row i)

    // col bias
    {
        float mq = 0.f;
        for (int d = q; d < DD; d += 4) {
            float m = means[grp * DD + d];
            mq += m * m * g_rvar[d];
        }
        mq += __shfl_xor_sync(0xffffffffu, mq, 1);
        mq += __shfl_xor_sync(0xffffffffu, mq, 2);
        if (q == 0) g_colbias[grp] = c - 0.5f * mq;
    }

    // At[j][i] = exp(tparams[i][j] - lse_j'(tparams[i][:]))
    {
        float mx = -1e30f;
        for (int jj = q; jj < SS; jj += 4) mx = fmaxf(mx, tparams[grp * SS + jj]);
        mx = fmaxf(mx, __shfl_xor_sync(0xffffffffu, mx, 1));
        mx = fmaxf(mx, __shfl_xor_sync(0xffffffffu, mx, 2));
        float se = 0.f;
        for (int jj = q; jj < SS; jj += 4) se += __expf(tparams[grp * SS + jj] - mx);
        se += __shfl_xor_sync(0xffffffffu, se, 1);
        se += __shfl_xor_sync(0xffffffffu, se, 2);
        float lse = mx + __logf(se);
        for (int jj = q; jj < SS; jj += 4)
            g_At[jj * SS + grp] = __float2bfloat16(__expf(tparams[grp * SS + jj] - lse));
    }

    // Mv = mu / var in bf16
    for (int idx = t; idx < SS * DD; idx += 512) {
        int d = idx & (DD - 1);
        g_Mv[idx] = __float2bfloat16(means[idx] * g_rvar[d]);
    }
}

// =====================================================================
// Kernel 2: per-row -0.5*sum(x^2/var) + bf16 cast of X (DRAM-bound)
// =====================================================================
__global__ __launch_bounds__(256) void xqcast_kernel(const float* __restrict__ sents) {
    __shared__ __align__(16) float srv[DD];
    int tid = threadIdx.x;
    for (int i = tid; i < DD; i += 256) srv[i] = g_rvar[i];
    __syncthreads();

    int warp = tid >> 5, lane = tid & 31;
    int row = blockIdx.x * 8 + warp;

    const float4* src = reinterpret_cast<const float4*>(sents + (size_t)row * DD);
    float sum = 0.f;
#pragma unroll
    for (int c = 0; c < 4; ++c) {
        int idx4 = c * 32 + lane;
        float4 x  = src[idx4];
        float4 rv = *reinterpret_cast<const float4*>(&srv[idx4 * 4]);
        sum += x.x * x.x * rv.x + x.y * x.y * rv.y + x.z * x.z * rv.z + x.w * x.w * rv.w;
        __nv_bfloat162 p0 = __float22bfloat162_rn(make_float2(x.x, x.y));
        __nv_bfloat162 p1 = __float22bfloat162_rn(make_float2(x.z, x.w));
        __nv_bfloat162* dst = reinterpret_cast<__nv_bfloat162*>(&g_Xs[(size_t)row * DD + idx4 * 4]);
        dst[0] = p0;
        dst[1] = p1;
    }
#pragma unroll
    for (int off = 16; off > 0; off >>= 1)
        sum += __shfl_xor_sync(0xffffffffu, sum, off);
    if (lane == 0) g_xq[row] = -0.5f * sum;
}

// =====================================================================
// Kernel 3: density GEMM — 2D warp tiling (4m x 2n), full ldmatrix.
// E staged in retired sA smem as [b8][j][bi], then block-copied (32KB contig).
// =====================================================================
#define SMSTRIDE 72

__global__ __launch_bounds__(256) void density_kernel() {
    __shared__ __align__(16) __nv_bfloat16 sA[128 * SMSTRIDE];
    __shared__ __align__(16) __nv_bfloat16 sB[128 * SMSTRIDE];
    __shared__ float scb[128];
    __shared__ float sMX[2][128];

    int tid  = threadIdx.x;
    int warp = tid >> 5, lane = tid & 31;
    int g = lane >> 2, tg = lane & 3;
    int warp_m = warp >> 1, warp_n = warp & 1;
    int mbase = blockIdx.x * 128;

    if (tid < 128) scb[tid] = g_colbias[tid];

    int arow = (lane & 7) + ((lane & 8) ? 8 : 0);
    int akof = (lane & 16) ? 8 : 0;
    int q = lane >> 3, r = lane & 7;
    int rowb = ((q & 2) ? 8 : 0) + r;
    int kofs = (q & 1) ? 8 : 0;

    uint32_t sa_base = smem_u32(sA);
    uint32_t sb_base = smem_u32(sB);

    float acc[2][8][4];
#pragma unroll
    for (int mt = 0; mt < 2; ++mt)
#pragma unroll
        for (int n = 0; n < 8; ++n)
#pragma unroll
            for (int k = 0; k < 4; ++k) acc[mt][n][k] = 0.f;

    __syncthreads();

    for (int ko = 0; ko < 8; ++ko) {
#pragma unroll
        for (int k = 0; k < 4; ++k) {
            int idx = tid + k * 256;
            int rr = idx >> 3, c8 = idx & 7;
            uint4 va = *reinterpret_cast<const uint4*>(&g_Xs[(size_t)(mbase + rr) * DD + ko * 64 + c8 * 8]);
            *reinterpret_cast<uint4*>(&sA[rr * SMSTRIDE + c8 * 8]) = va;
        }
#pragma unroll
        for (int k = 0; k < 4; ++k) {
            int idx = tid + k * 256;
            int rr = idx >> 3, c8 = idx & 7;
            uint4 vb = *reinterpret_cast<const uint4*>(&g_Mv[(size_t)rr * DD + ko * 64 + c8 * 8]);
            *reinterpret_cast<uint4*>(&sB[rr * SMSTRIDE + c8 * 8]) = vb;
        }
        __syncthreads();

#pragma unroll
        for (int ks = 0; ks < 4; ++ks) {
            int kb = ks * 16;
            uint32_t afr[2][4];
#pragma unroll
            for (int mt = 0; mt < 2; ++mt)
                ldmx4(afr[mt][0], afr[mt][1], afr[mt][2], afr[mt][3],
                      sa_base + ((warp_m * 32 + mt * 16 + arow) * SMSTRIDE + kb + akof) * 2);
#pragma unroll
            for (int npair = 0; npair < 4; ++npair) {
                uint32_t t0, t1, t2, t3;
                ldmx4(t0, t1, t2, t3,
                      sb_base + ((warp_n * 64 + npair * 16 + rowb) * SMSTRIDE + kb + kofs) * 2);
#pragma unroll
                for (int mt = 0; mt < 2; ++mt) {
                    mma_bf16(acc[mt][2 * npair][0], acc[mt][2 * npair][1],
                             acc[mt][2 * npair][2], acc[mt][2 * npair][3],
                             afr[mt][0], afr[mt][1], afr[mt][2], afr[mt][3], t0, t1);
                    mma_bf16(acc[mt][2 * npair + 1][0], acc[mt][2 * npair + 1][1],
                             acc[mt][2 * npair + 1][2], acc[mt][2 * npair + 1][3],
                             afr[mt][0], afr[mt][1], afr[mt][2], afr[mt][3], t2, t3);
                }
            }
        }
        __syncthreads();
    }

    // colbias + row maxes
    float mx[2][2];
    mx[0][0] = mx[0][1] = mx[1][0] = mx[1][1] = -1e30f;
#pragma unroll
    for (int mt = 0; mt < 2; ++mt)
#pragma unroll
        for (int n = 0; n < 8; ++n) {
            int cglob = (warp_n * 8 + n) * 8 + tg * 2;
            float cb0 = scb[cglob], cb1 = scb[cglob + 1];
            acc[mt][n][0] += cb0; acc[mt][n][1] += cb1;
            acc[mt][n][2] += cb0; acc[mt][n][3] += cb1;
            mx[mt][0] = fmaxf(mx[mt][0], fmaxf(acc[mt][n][0], acc[mt][n][1]));
            mx[mt][1] = fmaxf(mx[mt][1], fmaxf(acc[mt][n][2], acc[mt][n][3]));
        }
#pragma unroll
    for (int mt = 0; mt < 2; ++mt)
#pragma unroll
        for (int h = 0; h < 2; ++h) {
            mx[mt][h] = fmaxf(mx[mt][h], __shfl_xor_sync(0xffffffffu, mx[mt][h], 1));
            mx[mt][h] = fmaxf(mx[mt][h], __shfl_xor_sync(0xffffffffu, mx[mt][h], 2));
        }
    if (tg == 0) {
#pragma unroll
        for (int mt = 0; mt < 2; ++mt) {
            int rbase = warp_m * 32 + mt * 16;
            sMX[warp_n][rbase + g]     = mx[mt][0];
            sMX[warp_n][rbase + g + 8] = mx[mt][1];
        }
    }
    __syncthreads();

    int l = mbase >> 9;
    int bl0 = mbase & (BB - 1);    // first batch of this tile

    // write E into staging (reuse sA): stage[(b_local>>3)*1024 + j*8 + (b_local&7)]
    __nv_bfloat16* stage = sA;
#pragma unroll
    for (int mt = 0; mt < 2; ++mt) {
        int rbase = warp_m * 32 + mt * 16;
        float fmx0 = fmaxf(sMX[0][rbase + g], sMX[1][rbase + g]);
        float fmx1 = fmaxf(sMX[0][rbase + g + 8], sMX[1][rbase + g + 8]);
        int base0 = ((rbase >> 3)) * 1024 + g;        // b_local = rbase+g
        int base1 = ((rbase >> 3) + 1) * 1024 + g;    // b_local = rbase+g+8
#pragma unroll
        for (int n = 0; n < 8; ++n) {
            int j0 = (warp_n * 8 + n) * 8 + 2 * tg;
            stage[base0 + j0 * 8]       = __float2bfloat16(fexp(acc[mt][n][0] - fmx0));
            stage[base0 + (j0 + 1) * 8] = __float2bfloat16(fexp(acc[mt][n][1] - fmx0));
            stage[base1 + j0 * 8]       = __float2bfloat16(fexp(acc[mt][n][2] - fmx1));
            stage[base1 + (j0 + 1) * 8] = __float2bfloat16(fexp(acc[mt][n][3] - fmx1));
        }
        if (warp_n == 0 && tg == 0) {
            int r0 = mbase + rbase + g;
            int b = r0 & (BB - 1);
            g_dmaxT[(size_t)b * LL + l]       = fmx0 + g_xq[r0];
            g_dmaxT[(size_t)(b + 8) * LL + l] = fmx1 + g_xq[r0 + 8];
        }
    }
    __syncthreads();

    // contiguous 32 KB copy out
    uint4* dst = reinterpret_cast<uint4*>(g_E + ((size_t)l * 64 + (bl0 >> 3)) * 1024);
    const uint4* srcp = reinterpret_cast<const uint4*>(stage);
    for (int i = tid; i < 2048; i += 256) dst[i] = srcp[i];
}

// =====================================================================
// Kernel 4: forward recurrence — TRANSPOSED: out(j,b) = At(j,i) @ pT(i,b).
// 64 CTAs x 256 threads, 8 batches/CTA (n = 8, exactly one n-tile).
// Warp w owns m-tile j in [16w,16w+16): 8 HMMA/step; 64 HMMA/CTA/step.
// At fragments hoisted to regs; p (8 x 128) exchanged via smem, 1 BAR/step.
// =====================================================================
#define ATSTRIDE 136
#define PSTRIDE  136

__global__ __launch_bounds__(256) void recur_kernel(const float* __restrict__ masks) {
    __shared__ __align__(16) __nv_bfloat16 sAt[128 * ATSTRIDE];  // 34816 B
    __shared__ __align__(16) __nv_bfloat16 sP[2][8 * PSTRIDE];   // 2 x 2176 B
    __shared__ float sdmax[LL * 8];                              // 4096 B
    __shared__ unsigned char smk[LL * 8];                        // 1024 B
    __shared__ float srn[8][8];
    __shared__ float ssum[8][8];
    __shared__ float sM[8];

    int tid   = threadIdx.x;
    int lane  = tid & 31, w = tid >> 5;     // w in [0,8) = m-tile (j group)
    int b8    = blockIdx.x;                  // 0..63
    int b0    = b8 * 8;
    int g = lane >> 2, tg = lane & 3;

    {
        const uint4* src = reinterpret_cast<const uint4*>(g_At);
        for (int idx = tid; idx < 2048; idx += 256) {
            int j = idx >> 4, c = idx & 15;
            *reinterpret_cast<uint4*>(&sAt[j * ATSTRIDE + c * 8]) = src[idx];
        }
    }
    for (int idx = tid; idx < 1024; idx += 256) {
        int bi = idx >> 7, l = idx & 127;
        sdmax[l * 8 + bi] = g_dmaxT[(size_t)(b0 + bi) * LL + l];
        smk[l * 8 + bi]   = (masks[l * BB + b0 + bi] >= 0.5f) ? 1 : 0;
    }
    __syncthreads();

    // hoist At fragments for own m-tile (j in [16w,16w+16))
    int arow = (lane & 7) + ((lane & 8) ? 8 : 0);
    int akof = (lane & 16) ? 8 : 0;
    uint32_t af[32];
#pragma unroll
    for (int kt = 0; kt < 8; ++kt)
        ldmx4(af[kt * 4 + 0], af[kt * 4 + 1], af[kt * 4 + 2], af[kt * 4 + 3],
              smem_u32(&sAt[(16 * w + arow) * ATSTRIDE + kt * 16 + akof]));

    int j0 = 16 * w + g;
    int j1 = j0 + 8;

    // init: p = E[0]
    uint32_t pv01, pv23;   // {b=2tg, b=2tg+1} for rows j0 / j1
    {
        const __nv_bfloat16* E0 = g_E + (size_t)b8 * 1024;
        pv01 = *reinterpret_cast<const uint32_t*>(&E0[j0 * 8 + 2 * tg]);
        pv23 = *reinterpret_cast<const uint32_t*>(&E0[j1 * 8 + 2 * tg]);
        __nv_bfloat162 v01 = upk(pv01), v23 = upk(pv23);
        sP[0][(2 * tg) * PSTRIDE + j0]     = __low2bfloat16(v01);
        sP[0][(2 * tg + 1) * PSTRIDE + j0] = __high2bfloat16(v01);
        sP[0][(2 * tg) * PSTRIDE + j1]     = __low2bfloat16(v23);
        sP[0][(2 * tg + 1) * PSTRIDE + j1] = __high2bfloat16(v23);
    }
    float Mb0 = LOGPI_INIT + sdmax[2 * tg];
    float Mb1 = LOGPI_INIT + sdmax[2 * tg + 1];
    __syncthreads();

    // B-frag ldmatrix lane addresses over sP: [b rows][i cols]
    int br = lane & 7, bq = lane >> 3;
    uint32_t pb[2];
    pb[0] = smem_u32(&sP[0][br * PSTRIDE + 8 * bq]);
    pb[1] = smem_u32(&sP[1][br * PSTRIDE + 8 * bq]);

    int buf = 0;
    for (int l = 1; l < LL; ++l) {
        // B fragments: 4 x ldmx4 covering kt pairs
        uint32_t bfr[16];
#pragma unroll
        for (int ks = 0; ks < 4; ++ks)
            ldmx4(bfr[ks * 4 + 0], bfr[ks * 4 + 1], bfr[ks * 4 + 2], bfr[ks * 4 + 3],
                  pb[buf] + ks * 64);      // 32 halfs = 64 B per ks

        const __nv_bfloat16* El = g_E + ((size_t)l * 64 + b8) * 1024;
        uint32_t e01 = *reinterpret_cast<const uint32_t*>(&El[j0 * 8 + 2 * tg]);
        uint32_t e23 = *reinterpret_cast<const uint32_t*>(&El[j1 * 8 + 2 * tg]);

        float dm0 = sdmax[l * 8 + 2 * tg];
        float dm1 = sdmax[l * 8 + 2 * tg + 1];
        int mk0 = smk[l * 8 + 2 * tg];
        int mk1 = smk[l * 8 + 2 * tg + 1];

        float c0 = 0.f, c1 = 0.f, c2 = 0.f, c3 = 0.f;
#pragma unroll
        for (int kt = 0; kt < 8; ++kt)
            mma_bf16(c0, c1, c2, c3,
                     af[kt * 4 + 0], af[kt * 4 + 1], af[kt * 4 + 2], af[kt * 4 + 3],
                     bfr[kt * 2 + 0], bfr[kt * 2 + 1]);

        // epilogue: * E, per-batch-column mask blend
        float2 eg = __bfloat1622float2(upk(e01));
        float2 eh = __bfloat1622float2(upk(e23));
        float n0 = c0 * eg.x, n1 = c1 * eg.y;
        float n2 = c2 * eh.x, n3 = c3 * eh.y;
        float2 p01 = __bfloat1622float2(upk(pv01));
        float2 p23 = __bfloat1622float2(upk(pv23));
        if (!mk0) { n0 = p01.x; n2 = p23.x; }
        if (!mk1) { n1 = p01.y; n3 = p23.y; }
        if (mk0) Mb0 += dm0;
        if (mk1) Mb1 += dm1;

        // periodic renorm: per-batch max over all j
        if ((l & 7) == 0) {
            float m0 = fmaxf(1e-30f, fmaxf(n0, n2));
            float m1 = fmaxf(1e-30f, fmaxf(n1, n3));
#pragma unroll
            for (int off = 4; off <= 16; off <<= 1) {
                m0 = fmaxf(m0, __shfl_xor_sync(0xffffffffu, m0, off));
                m1 = fmaxf(m1, __shfl_xor_sync(0xffffffffu, m1, off));
            }
            if (lane < 4) { srn[w][2 * tg] = m0; srn[w][2 * tg + 1] = m1; }
            __syncthreads();
#pragma unroll
            for (int ww = 0; ww < 8; ++ww) {
                m0 = fmaxf(m0, srn[ww][2 * tg]);
                m1 = fmaxf(m1, srn[ww][2 * tg + 1]);
            }
            float r0i = 1.f / m0, r1i = 1.f / m1;
            n0 *= r0i; n2 *= r0i;
            n1 *= r1i; n3 *= r1i;
            Mb0 += __logf(m0);
            Mb1 += __logf(m1);
        }

        pv01 = pk(__floats2bfloat162_rn(n0, n1));
        pv23 = pk(__floats2bfloat162_rn(n2, n3));

        int nbuf = buf ^ 1;
        {
            __nv_bfloat16* base = sP[nbuf];
            base[(2 * tg) * PSTRIDE + j0]     = __float2bfloat16(n0);
            base[(2 * tg + 1) * PSTRIDE + j0] = __float2bfloat16(n1);
            base[(2 * tg) * PSTRIDE + j1]     = __float2bfloat16(n2);
            base[(2 * tg + 1) * PSTRIDE + j1] = __float2bfloat16(n3);
        }
        __syncthreads();
        buf = nbuf;
    }

    // objective per batch: M + log(sum_j p_j)
    float2 p01 = __bfloat1622float2(upk(pv01));
    float2 p23 = __bfloat1622float2(upk(pv23));
    float S0 = p01.x + p23.x;
    float S1 = p01.y + p23.y;
#pragma unroll
    for (int off = 4; off <= 16; off <<= 1) {
        S0 += __shfl_xor_sync(0xffffffffu, S0, off);
        S1 += __shfl_xor_sync(0xffffffffu, S1, off);
    }
    if (lane < 4) {
        ssum[w][2 * tg] = S0;
        ssum[w][2 * tg + 1] = S1;
        if (w == 0) { sM[2 * tg] = Mb0; sM[2 * tg + 1] = Mb1; }
    }
    __syncthreads();
    if (tid < 8) {
        float S = 0.f;
#pragma unroll
        for (int ww = 0; ww < 8; ++ww) S += ssum[ww][tid];
        S = fmaxf(S, 1e-37f);
        g_perb[b0 + tid] = sM[tid] + __logf(S);
    }
}

// =====================================================================
// Kernel 5: deterministic final reduction over 512 batch rows
// =====================================================================
__global__ void finalize_kernel(float* __restrict__ out, int out_size) {
    __shared__ float s[256];
    int t = threadIdx.x;
    s[t] = g_perb[t] + g_perb[t + 256];
    __syncthreads();
    for (int off = 128; off > 0; off >>= 1) {
        if (t < off) s[t] += s[t + off];
        __syncthreads();
    }
    for (int i = t; i < out_size; i += 256)
        if (i != 0) out[i] = 0.f;   // jacobian_loss = 0
    if (t == 0) out[0] = s[0];
}

// =====================================================================
extern "C" void kernel_launch(void* const* d_in, const int* in_sizes, int n_in,
                              void* d_out, int out_size) {
    const float* sents   = (const float*)d_in[0];
    const float* masks   = (const float*)d_in[1];
    const float* tparams = (const float*)d_in[2];
    const float* means   = (const float*)d_in[3];
    const float* var     = (const float*)d_in[4];
    float* out = (float*)d_out;

    prep_kernel<<<1, 512>>>(tparams, means, var);
    xqcast_kernel<<<LB / 8, 256>>>(sents);
    density_kernel<<<LB / 128, 256>>>();
    recur_kernel<<<64, 256>>>(masks);
    finalize_kernel<<<1, 256>>>(out, out_size);
}

// round 16
// speedup vs baseline: 1.2214x; 1.0076x over previous
#include <cuda_runtime.h>
#include <cuda_bf16.h>
#include <cstdint>
#include <math.h>

// Problem constants
#define LL 128
#define BB 512
#define DD 512
#define SS 128
#define LB (LL * BB)   // 65536

// -------- device scratch --------
__device__ __align__(16) float          g_colbias[SS];
__device__ __align__(16) float          g_rvar[DD];
__device__ __align__(16) float          g_xq[LB];               // -0.5*sum x^2/var
__device__ __align__(16) __nv_bfloat16  g_Xs[(size_t)LB * DD];  // X in bf16 (64 MB)
__device__ __align__(16) __nv_bfloat16  g_Mv[SS * DD];          // mu/var bf16, [s][d]
__device__ __align__(16) __nv_bfloat16  g_At[SS * SS];          // A^T bf16, [j][i]
// E bf16, layout [l][b>>3][j][b&7]  (16 MB)
__device__ __align__(16) __nv_bfloat16  g_E[(size_t)LL * 64 * 128 * 8];
__device__ __align__(16) float          g_dmaxT[BB * LL];       // dmax transposed: [b][l]
__device__ __align__(16) float          g_perb[BB];

#define LOG2PI 1.8378770664093453f
#define LOGPI_INIT (-4.852030263919617f)   // -log(128)

// ---- fast exp on the FMA pipe (x <= 0 expected; flushes below -80) ----
__device__ __forceinline__ float fexp(float x) {
    float t = fmaf(x, 1.4426950408889634f, 12582912.0f);
    int   ni = __float_as_int(t) - 0x4B400000;
    float n  = t - 12582912.0f;
    float f  = fmaf(x, 1.4426950408889634f, -n);
    float r  = 0.0013333558f;
    r = fmaf(r, f, 0.0096181291f);
    r = fmaf(r, f, 0.0555041087f);
    r = fmaf(r, f, 0.2402264689f);
    r = fmaf(r, f, 0.6931471806f);
    r = fmaf(r, f, 1.0f);
    float res = __int_as_float(__float_as_int(r) + (ni << 23));
    return (x > -80.0f) ? res : 0.0f;
}

__device__ __forceinline__ uint32_t pk(__nv_bfloat162 v) { return *reinterpret_cast<uint32_t*>(&v); }
__device__ __forceinline__ __nv_bfloat162 upk(uint32_t v) { return *reinterpret_cast<__nv_bfloat162*>(&v); }
__device__ __forceinline__ uint32_t smem_u32(const void* p) {
    return (uint32_t)__cvta_generic_to_shared(p);
}

__device__ __forceinline__ void mma_bf16(float& c0, float& c1, float& c2, float& c3,
                                         uint32_t a0, uint32_t a1, uint32_t a2, uint32_t a3,
                                         uint32_t b0, uint32_t b1) {
    asm volatile(
        "mma.sync.aligned.m16n8k16.row.col.f32.bf16.bf16.f32 "
        "{%0,%1,%2,%3}, {%4,%5,%6,%7}, {%8,%9}, {%0,%1,%2,%3};\n"
        : "+f"(c0), "+f"(c1), "+f"(c2), "+f"(c3)
        : "r"(a0), "r"(a1), "r"(a2), "r"(a3), "r"(b0), "r"(b1));
}

__device__ __forceinline__ void ldmx4(uint32_t& r0, uint32_t& r1, uint32_t& r2, uint32_t& r3,
                                      uint32_t addr) {
    asm volatile("ldmatrix.sync.aligned.m8n8.x4.shared.b16 {%0,%1,%2,%3}, [%4];"
                 : "=r"(r0), "=r"(r1), "=r"(r2), "=r"(r3) : "r"(addr));
}

// =====================================================================
// Kernel 1: preprocessing (1 block, 512 threads)
// =====================================================================
__global__ void prep_kernel(const float* __restrict__ tparams,
                            const float* __restrict__ means,
                            const float* __restrict__ var) {
    __shared__ float sred[512];
    int t = threadIdx.x;

    float v = var[t];
    g_rvar[t] = 1.0f / v;
    sred[t] = logf(v);
    __syncthreads();
    for (int off = 256; off > 0; off >>= 1) {
        if (t < off) sred[t] += sred[t + off];
        __syncthreads();
    }
    float slv = sred[0];
    float c = -256.0f * LOG2PI - 0.5f * slv;

    int q   = t & 3;      // 0..3
    int grp = t >> 2;     // 0..127  (row i)

    // col bias
    {
        float mq = 0.f;
        for (int d = q; d < DD; d += 4) {
            float m = means[grp * DD + d];
            mq += m * m * g_rvar[d];
        }
        mq += __shfl_xor_sync(0xffffffffu, mq, 1);
        mq += __shfl_xor_sync(0xffffffffu, mq, 2);
        if (q == 0) g_colbias[grp] = c - 0.5f * mq;
    }

    // At[j][i] = exp(tparams[i][j] - lse_j'(tparams[i][:]))
    {
        float mx = -1e30f;
        for (int jj = q; jj < SS; jj += 4) mx = fmaxf(mx, tparams[grp * SS + jj]);
        mx = fmaxf(mx, __shfl_xor_sync(0xffffffffu, mx, 1));
        mx = fmaxf(mx, __shfl_xor_sync(0xffffffffu, mx, 2));
        float se = 0.f;
        for (int jj = q; jj < SS; jj += 4) se += __expf(tparams[grp * SS + jj] - mx);
        se += __shfl_xor_sync(0xffffffffu, se, 1);
        se += __shfl_xor_sync(0xffffffffu, se, 2);
        float lse = mx + __logf(se);
        for (int jj = q; jj < SS; jj += 4)
            g_At[jj * SS + grp] = __float2bfloat16(__expf(tparams[grp * SS + jj] - lse));
    }

    // Mv = mu / var in bf16
    for (int idx = t; idx < SS * DD; idx += 512) {
        int d = idx & (DD - 1);
        g_Mv[idx] = __float2bfloat16(means[idx] * g_rvar[d]);
    }
}

// =====================================================================
// Kernel 2: per-row -0.5*sum(x^2/var) + bf16 cast of X (DRAM-bound)
// =====================================================================
__global__ __launch_bounds__(256) void xqcast_kernel(const float* __restrict__ sents) {
    __shared__ __align__(16) float srv[DD];
    int tid = threadIdx.x;
    for (int i = tid; i < DD; i += 256) srv[i] = g_rvar[i];
    __syncthreads();

    int warp = tid >> 5, lane = tid & 31;
    int row = blockIdx.x * 8 + warp;

    const float4* src = reinterpret_cast<const float4*>(sents + (size_t)row * DD);
    float sum = 0.f;
#pragma unroll
    for (int c = 0; c < 4; ++c) {
        int idx4 = c * 32 + lane;
        float4 x  = src[idx4];
        float4 rv = *reinterpret_cast<const float4*>(&srv[idx4 * 4]);
        sum += x.x * x.x * rv.x + x.y * x.y * rv.y + x.z * x.z * rv.z + x.w * x.w * rv.w;
        __nv_bfloat162 p0 = __float22bfloat162_rn(make_float2(x.x, x.y));
        __nv_bfloat162 p1 = __float22bfloat162_rn(make_float2(x.z, x.w));
        __nv_bfloat162* dst = reinterpret_cast<__nv_bfloat162*>(&g_Xs[(size_t)row * DD + idx4 * 4]);
        dst[0] = p0;
        dst[1] = p1;
    }
#pragma unroll
    for (int off = 16; off > 0; off >>= 1)
        sum += __shfl_xor_sync(0xffffffffu, sum, off);
    if (lane == 0) g_xq[row] = -0.5f * sum;
}

// =====================================================================
// Kernel 3: density GEMM — 2D warp tiling (4m x 2n), full ldmatrix.
// E staged in retired sA smem as [b8][j][bi], then block-copied (32KB contig).
// =====================================================================
#define SMSTRIDE 72

__global__ __launch_bounds__(256) void density_kernel() {
    __shared__ __align__(16) __nv_bfloat16 sA[128 * SMSTRIDE];
    __shared__ __align__(16) __nv_bfloat16 sB[128 * SMSTRIDE];
    __shared__ float scb[128];
    __shared__ float sMX[2][128];

    int tid  = threadIdx.x;
    int warp = tid >> 5, lane = tid & 31;
    int g = lane >> 2, tg = lane & 3;
    int warp_m = warp >> 1, warp_n = warp & 1;
    int mbase = blockIdx.x * 128;

    if (tid < 128) scb[tid] = g_colbias[tid];

    int arow = (lane & 7) + ((lane & 8) ? 8 : 0);
    int akof = (lane & 16) ? 8 : 0;
    int q = lane >> 3, r = lane & 7;
    int rowb = ((q & 2) ? 8 : 0) + r;
    int kofs = (q & 1) ? 8 : 0;

    uint32_t sa_base = smem_u32(sA);
    uint32_t sb_base = smem_u32(sB);

    float acc[2][8][4];
#pragma unroll
    for (int mt = 0; mt < 2; ++mt)
#pragma unroll
        for (int n = 0; n < 8; ++n)
#pragma unroll
            for (int k = 0; k < 4; ++k) acc[mt][n][k] = 0.f;

    __syncthreads();

    for (int ko = 0; ko < 8; ++ko) {
#pragma unroll
        for (int k = 0; k < 4; ++k) {
            int idx = tid + k * 256;
            int rr = idx >> 3, c8 = idx & 7;
            uint4 va = *reinterpret_cast<const uint4*>(&g_Xs[(size_t)(mbase + rr) * DD + ko * 64 + c8 * 8]);
            *reinterpret_cast<uint4*>(&sA[rr * SMSTRIDE + c8 * 8]) = va;
        }
#pragma unroll
        for (int k = 0; k < 4; ++k) {
            int idx = tid + k * 256;
            int rr = idx >> 3, c8 = idx & 7;
            uint4 vb = *reinterpret_cast<const uint4*>(&g_Mv[(size_t)rr * DD + ko * 64 + c8 * 8]);
            *reinterpret_cast<uint4*>(&sB[rr * SMSTRIDE + c8 * 8]) = vb;
        }
        __syncthreads();

#pragma unroll
        for (int ks = 0; ks < 4; ++ks) {
            int kb = ks * 16;
            uint32_t afr[2][4];
#pragma unroll
            for (int mt = 0; mt < 2; ++mt)
                ldmx4(afr[mt][0], afr[mt][1], afr[mt][2], afr[mt][3],
                      sa_base + ((warp_m * 32 + mt * 16 + arow) * SMSTRIDE + kb + akof) * 2);
#pragma unroll
            for (int npair = 0; npair < 4; ++npair) {
                uint32_t t0, t1, t2, t3;
                ldmx4(t0, t1, t2, t3,
                      sb_base + ((warp_n * 64 + npair * 16 + rowb) * SMSTRIDE + kb + kofs) * 2);
#pragma unroll
                for (int mt = 0; mt < 2; ++mt) {
                    mma_bf16(acc[mt][2 * npair][0], acc[mt][2 * npair][1],
                             acc[mt][2 * npair][2], acc[mt][2 * npair][3],
                             afr[mt][0], afr[mt][1], afr[mt][2], afr[mt][3], t0, t1);
                    mma_bf16(acc[mt][2 * npair + 1][0], acc[mt][2 * npair + 1][1],
                             acc[mt][2 * npair + 1][2], acc[mt][2 * npair + 1][3],
                             afr[mt][0], afr[mt][1], afr[mt][2], afr[mt][3], t2, t3);
                }
            }
        }
        __syncthreads();
    }

    // colbias + row maxes
    float mx[2][2];
    mx[0][0] = mx[0][1] = mx[1][0] = mx[1][1] = -1e30f;
#pragma unroll
    for (int mt = 0; mt < 2; ++mt)
#pragma unroll
        for (int n = 0; n < 8; ++n) {
            int cglob = (warp_n * 8 + n) * 8 + tg * 2;
            float cb0 = scb[cglob], cb1 = scb[cglob + 1];
            acc[mt][n][0] += cb0; acc[mt][n][1] += cb1;
            acc[mt][n][2] += cb0; acc[mt][n][3] += cb1;
            mx[mt][0] = fmaxf(mx[mt][0], fmaxf(acc[mt][n][0], acc[mt][n][1]));
            mx[mt][1] = fmaxf(mx[mt][1], fmaxf(acc[mt][n][2], acc[mt][n][3]));
        }
#pragma unroll
    for (int mt = 0; mt < 2; ++mt)
#pragma unroll
        for (int h = 0; h < 2; ++h) {
            mx[mt][h] = fmaxf(mx[mt][h], __shfl_xor_sync(0xffffffffu, mx[mt][h], 1));
            mx[mt][h] = fmaxf(mx[mt][h], __shfl_xor_sync(0xffffffffu, mx[mt][h], 2));
        }
    if (tg == 0) {
#pragma unroll
        for (int mt = 0; mt < 2; ++mt) {
            int rbase = warp_m * 32 + mt * 16;
            sMX[warp_n][rbase + g]     = mx[mt][0];
            sMX[warp_n][rbase + g + 8] = mx[mt][1];
        }
    }
    __syncthreads();

    int l = mbase >> 9;
    int bl0 = mbase & (BB - 1);    // first batch of this tile

    // write E into staging (reuse sA): stage[(b_local>>3)*1024 + j*8 + (b_local&7)]
    __nv_bfloat16* stage = sA;
#pragma unroll
    for (int mt = 0; mt < 2; ++mt) {
        int rbase = warp_m * 32 + mt * 16;
        float fmx0 = fmaxf(sMX[0][rbase + g], sMX[1][rbase + g]);
        float fmx1 = fmaxf(sMX[0][rbase + g + 8], sMX[1][rbase + g + 8]);
        int base0 = ((rbase >> 3)) * 1024 + g;        // b_local = rbase+g
        int base1 = ((rbase >> 3) + 1) * 1024 + g;    // b_local = rbase+g+8
#pragma unroll
        for (int n = 0; n < 8; ++n) {
            int j0 = (warp_n * 8 + n) * 8 + 2 * tg;
            stage[base0 + j0 * 8]       = __float2bfloat16(fexp(acc[mt][n][0] - fmx0));
            stage[base0 + (j0 + 1) * 8] = __float2bfloat16(fexp(acc[mt][n][1] - fmx0));
            stage[base1 + j0 * 8]       = __float2bfloat16(fexp(acc[mt][n][2] - fmx1));
            stage[base1 + (j0 + 1) * 8] = __float2bfloat16(fexp(acc[mt][n][3] - fmx1));
        }
        if (warp_n == 0 && tg == 0) {
            int r0 = mbase + rbase + g;
            int b = r0 & (BB - 1);
            g_dmaxT[(size_t)b * LL + l]       = fmx0 + g_xq[r0];
            g_dmaxT[(size_t)(b + 8) * LL + l] = fmx1 + g_xq[r0 + 8];
        }
    }
    __syncthreads();

    // contiguous 32 KB copy out
    uint4* dst = reinterpret_cast<uint4*>(g_E + ((size_t)l * 64 + (bl0 >> 3)) * 1024);
    const uint4* srcp = reinterpret_cast<const uint4*>(stage);
    for (int i = tid; i < 2048; i += 256) dst[i] = srcp[i];
}

// =====================================================================
// Kernel 4: forward recurrence — TRANSPOSED: out(j,b) = At(j,i) @ pT(i,b).
// 64 CTAs x 256 threads, 8 batches/CTA. Warp w owns j in [16w,16w+16).
// Split accumulator: two independent 4-deep HMMA chains (kt 0-3 / 4-7).
// =====================================================================
#define ATSTRIDE 136
#define PSTRIDE  136

__global__ __launch_bounds__(256) void recur_kernel(const float* __restrict__ masks) {
    __shared__ __align__(16) __nv_bfloat16 sAt[128 * ATSTRIDE];  // 34816 B
    __shared__ __align__(16) __nv_bfloat16 sP[2][8 * PSTRIDE];   // 2 x 2176 B
    __shared__ float sdmax[LL * 8];                              // 4096 B
    __shared__ unsigned char smk[LL * 8];                        // 1024 B
    __shared__ float srn[8][8];
    __shared__ float ssum[8][8];
    __shared__ float sM[8];

    int tid   = threadIdx.x;
    int lane  = tid & 31, w = tid >> 5;     // w in [0,8) = m-tile (j group)
    int b8    = blockIdx.x;                  // 0..63
    int b0    = b8 * 8;
    int g = lane >> 2, tg = lane & 3;

    {
        const uint4* src = reinterpret_cast<const uint4*>(g_At);
        for (int idx = tid; idx < 2048; idx += 256) {
            int j = idx >> 4, c = idx & 15;
            *reinterpret_cast<uint4*>(&sAt[j * ATSTRIDE + c * 8]) = src[idx];
        }
    }
    for (int idx = tid; idx < 1024; idx += 256) {
        int bi = idx >> 7, l = idx & 127;
        sdmax[l * 8 + bi] = g_dmaxT[(size_t)(b0 + bi) * LL + l];
        smk[l * 8 + bi]   = (masks[l * BB + b0 + bi] >= 0.5f) ? 1 : 0;
    }
    __syncthreads();

    // hoist At fragments for own m-tile (j in [16w,16w+16))
    int arow = (lane & 7) + ((lane & 8) ? 8 : 0);
    int akof = (lane & 16) ? 8 : 0;
    uint32_t af[32];
#pragma unroll
    for (int kt = 0; kt < 8; ++kt)
        ldmx4(af[kt * 4 + 0], af[kt * 4 + 1], af[kt * 4 + 2], af[kt * 4 + 3],
              smem_u32(&sAt[(16 * w + arow) * ATSTRIDE + kt * 16 + akof]));

    int j0 = 16 * w + g;
    int j1 = j0 + 8;

    // init: p = E[0]
    uint32_t pv01, pv23;   // {b=2tg, b=2tg+1} for rows j0 / j1
    {
        const __nv_bfloat16* E0 = g_E + (size_t)b8 * 1024;
        pv01 = *reinterpret_cast<const uint32_t*>(&E0[j0 * 8 + 2 * tg]);
        pv23 = *reinterpret_cast<const uint32_t*>(&E0[j1 * 8 + 2 * tg]);
        __nv_bfloat162 v01 = upk(pv01), v23 = upk(pv23);
        sP[0][(2 * tg) * PSTRIDE + j0]     = __low2bfloat16(v01);
        sP[0][(2 * tg + 1) * PSTRIDE + j0] = __high2bfloat16(v01);
        sP[0][(2 * tg) * PSTRIDE + j1]     = __low2bfloat16(v23);
        sP[0][(2 * tg + 1) * PSTRIDE + j1] = __high2bfloat16(v23);
    }
    float Mb0 = LOGPI_INIT + sdmax[2 * tg];
    float Mb1 = LOGPI_INIT + sdmax[2 * tg + 1];
    __syncthreads();

    // B-frag ldmatrix lane addresses over sP: [b rows][i cols]
    int br = lane & 7, bq = lane >> 3;
    uint32_t pb[2];
    pb[0] = smem_u32(&sP[0][br * PSTRIDE + 8 * bq]);
    pb[1] = smem_u32(&sP[1][br * PSTRIDE + 8 * bq]);

    int buf = 0;
    for (int l = 1; l < LL; ++l) {
        // B fragments: 4 x ldmx4 covering kt pairs
        uint32_t bfr[16];
#pragma unroll
        for (int ks = 0; ks < 4; ++ks)
            ldmx4(bfr[ks * 4 + 0], bfr[ks * 4 + 1], bfr[ks * 4 + 2], bfr[ks * 4 + 3],
                  pb[buf] + ks * 64);      // 32 halfs = 64 B per ks

        const __nv_bfloat16* El = g_E + ((size_t)l * 64 + b8) * 1024;
        uint32_t e01 = *reinterpret_cast<const uint32_t*>(&El[j0 * 8 + 2 * tg]);
        uint32_t e23 = *reinterpret_cast<const uint32_t*>(&El[j1 * 8 + 2 * tg]);

        float dm0 = sdmax[l * 8 + 2 * tg];
        float dm1 = sdmax[l * 8 + 2 * tg + 1];
        int mk0 = smk[l * 8 + 2 * tg];
        int mk1 = smk[l * 8 + 2 * tg + 1];

        // two independent 4-deep chains
        float a0c = 0.f, a1c = 0.f, a2c = 0.f, a3c = 0.f;
        float b0c = 0.f, b1c = 0.f, b2c = 0.f, b3c = 0.f;
#pragma unroll
        for (int kt = 0; kt < 4; ++kt)
            mma_bf16(a0c, a1c, a2c, a3c,
                     af[kt * 4 + 0], af[kt * 4 + 1], af[kt * 4 + 2], af[kt * 4 + 3],
                     bfr[kt * 2 + 0], bfr[kt * 2 + 1]);
#pragma unroll
        for (int kt = 4; kt < 8; ++kt)
            mma_bf16(b0c, b1c, b2c, b3c,
                     af[kt * 4 + 0], af[kt * 4 + 1], af[kt * 4 + 2], af[kt * 4 + 3],
                     bfr[kt * 2 + 0], bfr[kt * 2 + 1]);
        float c0 = a0c + b0c, c1 = a1c + b1c, c2 = a2c + b2c, c3 = a3c + b3c;

        // epilogue: * E, per-batch-column mask blend
        float2 eg = __bfloat1622float2(upk(e01));
        float2 eh = __bfloat1622float2(upk(e23));
        float n0 = c0 * eg.x, n1 = c1 * eg.y;
        float n2 = c2 * eh.x, n3 = c3 * eh.y;
        float2 p01 = __bfloat1622float2(upk(pv01));
        float2 p23 = __bfloat1622float2(upk(pv23));
        if (!mk0) { n0 = p01.x; n2 = p23.x; }
        if (!mk1) { n1 = p01.y; n3 = p23.y; }
        if (mk0) Mb0 += dm0;
        if (mk1) Mb1 += dm1;

        // periodic renorm: per-batch max over all j
        if ((l & 7) == 0) {
            float m0 = fmaxf(1e-30f, fmaxf(n0, n2));
            float m1 = fmaxf(1e-30f, fmaxf(n1, n3));
#pragma unroll
            for (int off = 4; off <= 16; off <<= 1) {
                m0 = fmaxf(m0, __shfl_xor_sync(0xffffffffu, m0, off));
                m1 = fmaxf(m1, __shfl_xor_sync(0xffffffffu, m1, off));
            }
            if (lane < 4) { srn[w][2 * tg] = m0; srn[w][2 * tg + 1] = m1; }
            __syncthreads();
#pragma unroll
            for (int ww = 0; ww < 8; ++ww) {
                m0 = fmaxf(m0, srn[ww][2 * tg]);
                m1 = fmaxf(m1, srn[ww][2 * tg + 1]);
            }
            float r0i = 1.f / m0, r1i = 1.f / m1;
            n0 *= r0i; n2 *= r0i;
            n1 *= r1i; n3 *= r1i;
            Mb0 += __logf(m0);
            Mb1 += __logf(m1);
        }

        pv01 = pk(__floats2bfloat162_rn(n0, n1));
        pv23 = pk(__floats2bfloat162_rn(n2, n3));

        int nbuf = buf ^ 1;
        {
            __nv_bfloat16* base = sP[nbuf];
            base[(2 * tg) * PSTRIDE + j0]     = __float2bfloat16(n0);
            base[(2 * tg + 1) * PSTRIDE + j0] = __float2bfloat16(n1);
            base[(2 * tg) * PSTRIDE + j1]     = __float2bfloat16(n2);
            base[(2 * tg + 1) * PSTRIDE + j1] = __float2bfloat16(n3);
        }
        __syncthreads();
        buf = nbuf;
    }

    // objective per batch: M + log(sum_j p_j)
    float2 p01 = __bfloat1622float2(upk(pv01));
    float2 p23 = __bfloat1622float2(upk(pv23));
    float S0 = p01.x + p23.x;
    float S1 = p01.y + p23.y;
#pragma unroll
    for (int off = 4; off <= 16; off <<= 1) {
        S0 += __shfl_xor_sync(0xffffffffu, S0, off);
        S1 += __shfl_xor_sync(0xffffffffu, S1, off);
    }
    if (lane < 4) {
        ssum[w][2 * tg] = S0;
        ssum[w][2 * tg + 1] = S1;
        if (w == 0) { sM[2 * tg] = Mb0; sM[2 * tg + 1] = Mb1; }
    }
    __syncthreads();
    if (tid < 8) {
        float S = 0.f;
#pragma unroll
        for (int ww = 0; ww < 8; ++ww) S += ssum[ww][tid];
        S = fmaxf(S, 1e-37f);
        g_perb[b0 + tid] = sM[tid] + __logf(S);
    }
}

// =====================================================================
// Kernel 5: deterministic final reduction over 512 batch rows
// =====================================================================
__global__ void finalize_kernel(float* __restrict__ out, int out_size) {
    __shared__ float s[256];
    int t = threadIdx.x;
    s[t] = g_perb[t] + g_perb[t + 256];
    __syncthreads();
    for (int off = 128; off > 0; off >>= 1) {
        if (t < off) s[t] += s[t + off];
        __syncthreads();
    }
    for (int i = t; i < out_size; i += 256)
        if (i != 0) out[i] = 0.f;   // jacobian_loss = 0
    if (t == 0) out[0] = s[0];
}

// =====================================================================
extern "C" void kernel_launch(void* const* d_in, const int* in_sizes, int n_in,
                              void* d_out, int out_size) {
    const float* sents   = (const float*)d_in[0];
    const float* masks   = (const float*)d_in[1];
    const float* tparams = (const float*)d_in[2];
    const float* means   = (const float*)d_in[3];
    const float* var     = (const float*)d_in[4];
    float* out = (float*)d_out;

    prep_kernel<<<1, 512>>>(tparams, means, var);
    xqcast_kernel<<<LB / 8, 256>>>(sents);
    density_kernel<<<LB / 128, 256>>>();
    recur_kernel<<<64, 256>>>(masks);
    finalize_kernel<<<1, 256>>>(out, out_size);
}